// round 11
// baseline (speedup 1.0000x reference)
#include <cuda_runtime.h>
#include <cuda_fp16.h>
#include <cstdint>

// ===========================================================================
// MaskedCouplingRQS — Round 11: R10 + transcendental eviction.
// Softmax/softplus exps -> FMA-pipe polynomial exp2 (MUFU 25 -> 7 per task);
// log2e folded into W4/b4 softmax params at prep; max-subtraction removed.
// ===========================================================================

#define THREADS 256
#define SA_H 160
#define SW_H 96
#define SRP  132

#define A_B    0
#define WA_B   40960
#define WB_B   65536
#define P_B    90112
#define B1_B   145024
#define B2_B   145536
#define B3_B   146048
#define B4_B   146560
#define LD_B   149760
#define SMEM_BYTES 151808

#define WPK_W1 0
#define WPK_W2 4096
#define WPK_W3 20480
#define WPK_W4 36864
#define W4_CH  13312
#define WPK_TOT 143360
__device__ __half g_wpk[WPK_TOT];

#define LOG2E 1.44269504f

// --------------------------- helpers ---------------------------------------
__device__ __forceinline__ void cp16(void* dst, const void* src) {
    uint32_t s = (uint32_t)__cvta_generic_to_shared(dst);
    asm volatile("cp.async.cg.shared.global [%0], [%1], 16;" :: "r"(s), "l"(src));
}
__device__ __forceinline__ void cp_commit() { asm volatile("cp.async.commit_group;"); }
template<int N>
__device__ __forceinline__ void cp_wait() {
    asm volatile("cp.async.wait_group %0;" :: "n"(N) : "memory");
}
__device__ __forceinline__ void mma16(float* c, uint32_t a0, uint32_t a1,
                                      uint32_t a2, uint32_t a3,
                                      uint32_t b0, uint32_t b1) {
    asm volatile(
        "mma.sync.aligned.m16n8k16.row.col.f32.f16.f16.f32 "
        "{%0,%1,%2,%3}, {%4,%5,%6,%7}, {%8,%9}, {%0,%1,%2,%3};"
        : "+f"(c[0]), "+f"(c[1]), "+f"(c[2]), "+f"(c[3])
        : "r"(a0), "r"(a1), "r"(a2), "r"(a3), "r"(b0), "r"(b1));
}
// exp2 via FMA pipe: magic-constant round + degree-5 poly; rel err ~2.4e-6
__device__ __forceinline__ float fast_exp2(float y) {
    y = fminf(fmaxf(y, -80.f), 80.f);
    float t = y + 12582912.f;                     // 1.5 * 2^23
    int ki = __float_as_int(t) - 0x4B400000;      // round(y)
    float r = y - (t - 12582912.f);               // r in [-0.5, 0.5]
    float p = 1.33335581e-3f;
    p = fmaf(p, r, 9.61812910e-3f);
    p = fmaf(p, r, 5.55041087e-2f);
    p = fmaf(p, r, 2.40226507e-1f);
    p = fmaf(p, r, 6.93147180e-1f);
    p = fmaf(p, r, 1.0f);
    return __int_as_float(__float_as_int(p) + (ki << 23));
}
__device__ __forceinline__ float softplus_f(float v) {
    float e = fast_exp2(-fabsf(v) * LOG2E);
    return fmaxf(v, 0.f) + __logf(1.f + e);
}
__device__ __forceinline__ int hpos(int k) {
    int rel = k & 31;
    return ((k >> 5) << 5) + (((rel >> 1) & 3) << 3) + ((rel >> 3) << 1) + (rel & 1);
}

// ---------------------------------------------------------------------------
// prep: pack weights to fp16 (R9-verified column map). W4 softmax-param rows
// (param index < 16 within each 25-group) are pre-scaled by log2e.
// ---------------------------------------------------------------------------
__global__ void prep_weights(const float* __restrict__ W1, const float* __restrict__ W2,
                             const float* __restrict__ W3, const float* __restrict__ W4)
{
    int idx = blockIdx.x * blockDim.x + threadIdx.x;
    if (idx >= WPK_TOT) return;
    float v;
    if (idx < WPK_W2) {                               // W1: 128 x 32 halves
        int n = idx >> 5, p = idx & 31;
        int mm = p >> 3, hh = p & 7;
        int k = 2 * mm + (hh & 1) + 8 * (hh >> 1);
        v = W1[n * 32 + k];
    } else if (idx < WPK_W4) {                        // W2/W3: k0,k1 [128][64]
        int t = idx - WPK_W2;
        const float* W = (t < 16384) ? W2 : W3;
        int r = t & 16383;
        int kh = r >> 13, rr = r & 8191;
        int n = rr >> 6, p = rr & 63;
        int kg = p >> 5, rem = p & 31, mm = rem >> 3, hh = rem & 7;
        int kl = kg * 32 + 2 * mm + (hh & 1) + 8 * (hh >> 1);
        v = W[n * 128 + kh * 64 + kl];
    } else {                                          // W4: 8 x (k0,k1) [104][64]
        int t = idx - WPK_W4;
        int c = t / W4_CH, r = t - c * W4_CH;
        int kh = (r >= 6656) ? 1 : 0;
        int rr = kh ? r - 6656 : r;
        int n = rr >> 6, p = rr & 63;
        int kg = p >> 5, rem = p & 31, mm = rem >> 3, hh = rem & 7;
        int kl = kg * 32 + 2 * mm + (hh & 1) + 8 * (hh >> 1);
        if (n < 100) {
            v = W4[(size_t)(c * 100 + n) * 128 + kh * 64 + kl];
            if ((n % 25) < 16) v *= LOG2E;            // fold log2e for softmax params
        } else v = 0.f;
    }
    g_wpk[idx] = __float2half_rn(v);
}

// ---------------------------------------------------------------------------
template<int ROWH>
__device__ __forceinline__ void stage_u(__half* dst, const __half* src, int nrows) {
    constexpr int CH = ROWH / 8;
    for (int i = threadIdx.x; i < nrows * CH; i += THREADS) {
        int row = i / CH, j = i - row * CH;
        cp16(dst + row * SW_H + j * 8, src + row * ROWH + j * 8);
    }
}

template<int NT, int KG>
__device__ __forceinline__ void mma_unit2(const __half* a0p, const __half* a1p,
                                          const __half* Wg, float* C) {
    #pragma unroll
    for (int kg = 0; kg < KG; kg++) {
        uint4 X0 = *(const uint4*)(a0p + kg * 32);
        uint4 Y0 = *(const uint4*)(a0p + 8 * SA_H + kg * 32);
        uint4 X1 = *(const uint4*)(a1p + kg * 32);
        uint4 Y1 = *(const uint4*)(a1p + 8 * SA_H + kg * 32);
        #pragma unroll
        for (int nt = 0; nt < NT; nt++) {
            uint4 Wv = *(const uint4*)(Wg + nt * 8 * SW_H + kg * 32);
            mma16(C + nt * 8,     X0.x, Y0.x, X0.y, Y0.y, Wv.x, Wv.y);
            mma16(C + nt * 8,     X0.z, Y0.z, X0.w, Y0.w, Wv.z, Wv.w);
            mma16(C + nt * 8 + 4, X1.x, Y1.x, X1.y, Y1.y, Wv.x, Wv.y);
            mma16(C + nt * 8 + 4, X1.z, Y1.z, X1.w, Y1.w, Wv.z, Wv.w);
        }
    }
}

__device__ __forceinline__ void relu_store2(const float* C, const float* bs,
                                            __half* Ah, int R0, int ng) {
    const int lane = threadIdx.x & 31;
    const int g = lane >> 2, m = lane & 3;
    #pragma unroll
    for (int mt = 0; mt < 2; mt++) {
        const int rb = R0 + mt * 16;
        #pragma unroll
        for (int nt = 0; nt < 8; nt++) {
            const int ntg = nt + ng * 8;
            const int c0 = ntg * 8 + 2 * m;
            const float b0 = bs[c0], b1 = bs[c0 + 1];
            const int off = ((ntg >> 2) << 5) + (m << 3) + ((ntg & 3) << 1);
            const float* Cc = C + nt * 8 + mt * 4;
            *(__half2*)(Ah + (rb + g) * SA_H + off) =
                __floats2half2_rn(fmaxf(Cc[0] + b0, 0.f), fmaxf(Cc[1] + b1, 0.f));
            *(__half2*)(Ah + (rb + g + 8) * SA_H + off) =
                __floats2half2_rn(fmaxf(Cc[2] + b0, 0.f), fmaxf(Cc[3] + b1, 0.f));
        }
    }
}

template<int NT>
__device__ __forceinline__ void p_store2(const float* C, float* P, int R0, int ng) {
    const int lane = threadIdx.x & 31;
    const int g = lane >> 2, m = lane & 3;
    #pragma unroll
    for (int mt = 0; mt < 2; mt++) {
        const int rb = R0 + mt * 16;
        #pragma unroll
        for (int nt = 0; nt < NT; nt++) {
            const int c0 = ng * 64 + nt * 8 + 2 * m;
            const float* Cc = C + nt * 8 + mt * 4;
            P[c0 * SRP + rb + g]           = Cc[0];
            P[(c0 + 1) * SRP + rb + g]     = Cc[1];
            P[c0 * SRP + rb + g + 8]       = Cc[2];
            P[(c0 + 1) * SRP + rb + g + 8] = Cc[3];
        }
    }
}

// ---------------------------------------------------------------------------
__global__ __launch_bounds__(THREADS, 1)
void rqs_mma_kernel(const float* __restrict__ x,
                    const float* __restrict__ b1, const float* __restrict__ b2,
                    const float* __restrict__ b3, const float* __restrict__ b4,
                    float* __restrict__ out, int B)
{
    extern __shared__ char smem[];
    __half* Ah  = (__half*)(smem + A_B);
    __half* WAb = (__half*)(smem + WA_B);
    __half* WBb = (__half*)(smem + WB_B);
    float*  Psm = (float*)(smem + P_B);
    float*  B1S = (float*)(smem + B1_B);
    float*  B2S = (float*)(smem + B2_B);
    float*  B3S = (float*)(smem + B3_B);
    float*  B4S = (float*)(smem + B4_B);
    float*  LDA = (float*)(smem + LD_B);

    const int tid  = threadIdx.x;
    const int lane = tid & 31;
    const int g    = lane >> 2, m = lane & 3;
    const int warp = tid >> 5;
    const int rg   = warp & 3;
    const int ng   = warp >> 2;
    const int R0   = rg * 32;
    const long row0 = (long)blockIdx.x * 128;

    const __half* aw0 = Ah + (R0 + g) * SA_H + m * 8;
    const __half* aw1 = aw0 + 16 * SA_H;
    const __half* WAg = WAb + (ng * 64 + g) * SW_H + m * 8;
    const __half* WBg = WBb + (ng * 64 + g) * SW_H + m * 8;
    const __half* gw  = g_wpk;

    // ---- g0: W1 + biases -> WA ; g1: W2k0 -> WB ----
    stage_u<32>(WAb, gw + WPK_W1, 128);
    for (int i = tid; i < 32; i += THREADS) {
        cp16(B1S + i * 4, b1 + i * 4);
        cp16(B2S + i * 4, b2 + i * 4);
        cp16(B3S + i * 4, b3 + i * 4);
    }
    for (int i = tid; i < 200; i += THREADS) cp16(B4S + i * 4, b4 + i * 4);
    cp_commit();
    stage_u<64>(WBb, gw + WPK_W2, 128); cp_commit();

    // ---- x_masked -> packed fp16 A ----
    for (int i = tid; i < 1024; i += THREADS) {
        int row = i >> 3, j = i & 7;
        float4 v = make_float4(0.f, 0.f, 0.f, 0.f);
        if (row0 + row < B) v = *(const float4*)(x + (row0 + row) * 64 + j * 4);
        __half* Ar = Ah + row * SA_H;
        Ar[hpos(j * 4 + 0)] = __float2half_rn(v.x);
        Ar[hpos(j * 4 + 1)] = __float2half_rn(v.y);
        Ar[hpos(j * 4 + 2)] = __float2half_rn(v.z);
        Ar[hpos(j * 4 + 3)] = __float2half_rn(v.w);
    }

    cp_wait<1>(); __syncthreads();
    // fold log2e into the softmax-param entries of b4 (once; read much later)
    for (int i = tid; i < 800; i += THREADS)
        if ((i % 25) < 16) B4S[i] *= LOG2E;

    float C[64];

    // ================= Layer 1 (K=32) =================
    #pragma unroll
    for (int i = 0; i < 64; i++) C[i] = 0.f;
    mma_unit2<8, 1>(aw0, aw1, WAg, C);
    __syncthreads(); stage_u<64>(WAb, gw + WPK_W2 + 8192, 128); cp_commit();   // W2k1
    relu_store2(C, B1S, Ah, R0, ng);                                           // h1

    // ================= Layer 2 =================
    #pragma unroll
    for (int i = 0; i < 64; i++) C[i] = 0.f;
    cp_wait<1>(); __syncthreads();
    mma_unit2<8, 2>(aw0, aw1, WBg, C);                                         // k0
    __syncthreads(); stage_u<64>(WBb, gw + WPK_W3, 128); cp_commit();          // W3k0
    cp_wait<1>(); __syncthreads();
    mma_unit2<8, 2>(aw0 + 64, aw1 + 64, WAg, C);                               // k1
    __syncthreads(); stage_u<64>(WAb, gw + WPK_W3 + 8192, 128); cp_commit();   // W3k1
    relu_store2(C, B2S, Ah, R0, ng);                                           // h2

    // ================= Layer 3 =================
    #pragma unroll
    for (int i = 0; i < 64; i++) C[i] = 0.f;
    cp_wait<1>(); __syncthreads();
    mma_unit2<8, 2>(aw0, aw1, WBg, C);
    __syncthreads(); stage_u<64>(WBb, gw + WPK_W4, 104); cp_commit();          // c0 k0
    cp_wait<1>(); __syncthreads();
    mma_unit2<8, 2>(aw0 + 64, aw1 + 64, WAg, C);
    __syncthreads(); stage_u<64>(WAb, gw + WPK_W4 + 6656, 104); cp_commit();   // c0 k1
    relu_store2(C, B3S, Ah, R0, ng);                                           // h3

    // ================= Layer 4 + spline, 8 chunks =================
    const float MINB = 1e-4f;
    const float FREE = 10.f - 8.f * 1e-4f;
    float ld0 = 0.f, ld1 = 0.f;

    #pragma unroll 1
    for (int c = 0; c < 8; c++) {
        const __half* nk = gw + WPK_W4 + (c + 1) * W4_CH;

        #pragma unroll
        for (int i = 0; i < 64; i++) C[i] = 0.f;

        cp_wait<1>(); __syncthreads();
        if (ng == 0) mma_unit2<8, 2>(aw0, aw1, WBg, C);
        else         mma_unit2<5, 2>(aw0, aw1, WBg, C);
        __syncthreads();
        if (c < 7) { stage_u<64>(WBb, nk, 104); cp_commit(); }
        if (c < 7) { cp_wait<1>(); } else { cp_wait<0>(); }
        __syncthreads();
        if (ng == 0) mma_unit2<8, 2>(aw0 + 64, aw1 + 64, WAg, C);
        else         mma_unit2<5, 2>(aw0 + 64, aw1 + 64, WAg, C);
        __syncthreads();
        if (c < 7) { stage_u<64>(WAb, nk + 6656, 104); cp_commit(); }
        if (ng == 0) p_store2<8>(C, Psm, R0, 0);
        else         p_store2<5>(C, Psm, R0, 1);
        __syncthreads();

        // -------- epilogue: warp handles dim rg, rows (ng+2s)*32+lane --------
        #pragma unroll
        for (int s = 0; s < 2; s++) {
            const int row = (ng + 2 * s) * 32 + lane;
            const int t   = c * 4 + rg;

            float acc[25];
            #pragma unroll
            for (int p = 0; p < 25; p++)
                acc[p] = Psm[(rg * 25 + p) * SRP + row] + B4S[c * 100 + rg * 25 + p];

            // softmax via poly exp2 (log2e pre-folded; no max subtraction)
            float wdt[8]; float Sw = 0.f;
            #pragma unroll
            for (int i = 0; i < 8; i++) { wdt[i] = fast_exp2(acc[i]); Sw += wdt[i]; }
            float hgt[8]; float Sh = 0.f;
            #pragma unroll
            for (int i = 0; i < 8; i++) { hgt[i] = fast_exp2(acc[8 + i]); Sh += hgt[i]; }
            const float fw = FREE / Sw, fh = FREE / Sh;
            #pragma unroll
            for (int i = 0; i < 8; i++) {
                wdt[i] = MINB + wdt[i] * fw;
                hgt[i] = MINB + hgt[i] * fh;
            }

            float xt = 0.f;
            const bool vr = (row0 + row) < B;
            if (vr) xt = x[(row0 + row) * 64 + 32 + t];
            const float xc = fminf(fmaxf(xt, -5.f), 5.f);
            const bool inside = (xt >= -5.f) && (xt <= 5.f);

            int idx = 0; float cum = -5.f, xk = -5.f, wk = wdt[0];
            #pragma unroll
            for (int i = 0; i < 7; i++) {
                cum += wdt[i];
                if (xc >= cum) { idx = i + 1; xk = cum; wk = wdt[i + 1]; }
            }
            float cumh = -5.f, yk = -5.f, hk = hgt[0];
            #pragma unroll
            for (int i = 0; i < 7; i++) {
                cumh += hgt[i];
                if (idx > i) { yk = cumh; hk = hgt[i + 1]; }
            }
            float sA = acc[16], sB = acc[17];
            #pragma unroll
            for (int i = 1; i < 8; i++)
                if (idx >= i) { sA = acc[16 + i]; sB = acc[17 + i]; }
            const float dk  = 1e-4f + softplus_f(sA);
            const float dk1 = 1e-4f + softplus_f(sB);

            const float rwk  = 1.f / wk;
            const float xi   = (xc - xk) * rwk;
            const float om   = 1.f - xi;
            const float sk   = hk * rwk;
            const float xiom = xi * om;
            const float den  = sk + (dk1 + dk - 2.f * sk) * xiom;
            const float rden = 1.f / den;
            const float num  = sk * xi * xi + dk * xiom;
            const float y_in = yk + hk * num * rden;
            const float num2 = dk1 * xi * xi + 2.f * sk * xiom + dk * om * om;
            const float ld_in = __logf(sk * sk * num2 * rden * rden);

            if (vr) out[(row0 + row) * 64 + 32 + t] = inside ? y_in : xt;
            const float ldv = inside ? ld_in : 0.f;
            if (s == 0) ld0 += ldv; else ld1 += ldv;
        }
    }

    // ---- logdet: 4 dim-partials per row via smem ----
    LDA[rg * 128 + ng * 32 + lane]       = ld0;
    LDA[rg * 128 + (ng + 2) * 32 + lane] = ld1;
    __syncthreads();
    if (tid < 128) {
        float v = LDA[tid] + LDA[128 + tid] + LDA[256 + tid] + LDA[384 + tid];
        if (row0 + tid < B) out[(size_t)B * 64 + row0 + tid] = v;
    }

    // ---- masked-column copy ----
    for (int i = tid; i < 1024; i += THREADS) {
        int row = i >> 3, j = i & 7;
        if (row0 + row < B)
            *(float4*)(out + (row0 + row) * 64 + j * 4) =
                *(const float4*)(x + (row0 + row) * 64 + j * 4);
    }
}

// ---------------------------------------------------------------------------
extern "C" void kernel_launch(void* const* d_in, const int* in_sizes, int n_in,
                              void* d_out, int out_size)
{
    const float* x  = (const float*)d_in[0];
    const float* W1 = (const float*)d_in[1];
    const float* b1 = (const float*)d_in[2];
    const float* W2 = (const float*)d_in[3];
    const float* b2 = (const float*)d_in[4];
    const float* W3 = (const float*)d_in[5];
    const float* b3 = (const float*)d_in[6];
    const float* W4 = (const float*)d_in[7];
    const float* b4 = (const float*)d_in[8];
    float* out = (float*)d_out;

    const int B = in_sizes[0] / 64;

    prep_weights<<<(WPK_TOT + 255) / 256, 256>>>(W1, W2, W3, W4);

    cudaFuncSetAttribute(rqs_mma_kernel,
                         cudaFuncAttributeMaxDynamicSharedMemorySize, SMEM_BYTES);
    const int grid = (B + 127) / 128;
    rqs_mma_kernel<<<grid, THREADS, SMEM_BYTES>>>(x, b1, b2, b3, b4, out, B);
}

// round 12
// speedup vs baseline: 1.1113x; 1.1113x over previous
#include <cuda_runtime.h>
#include <cuda_fp16.h>
#include <cstdint>

// ===========================================================================
// MaskedCouplingRQS — Round 12: 512 threads / 16 warps (4 per SMSP) to hide
// fixed-latency chains. Warp grid 4 rowgroups x 4 n-groups; epilogue 1 task
// per thread. Numerics identical to R9/R10 (MUFU path).
// ===========================================================================

#define THREADS 512
#define SA_H 160
#define SW_H 96
#define SRP  132

#define A_B    0
#define WA_B   40960
#define WB_B   65536
#define P_B    90112
#define B1_B   145024
#define B2_B   145536
#define B3_B   146048
#define B4_B   146560
#define LD_B   149760
#define SMEM_BYTES 151808

#define WPK_W1 0
#define WPK_W2 4096
#define WPK_W3 20480
#define WPK_W4 36864
#define W4_CH  13312
#define WPK_TOT 143360
__device__ __half g_wpk[WPK_TOT];

// --------------------------- helpers ---------------------------------------
__device__ __forceinline__ void cp16(void* dst, const void* src) {
    uint32_t s = (uint32_t)__cvta_generic_to_shared(dst);
    asm volatile("cp.async.cg.shared.global [%0], [%1], 16;" :: "r"(s), "l"(src));
}
__device__ __forceinline__ void cp_commit() { asm volatile("cp.async.commit_group;"); }
template<int N>
__device__ __forceinline__ void cp_wait() {
    asm volatile("cp.async.wait_group %0;" :: "n"(N) : "memory");
}
__device__ __forceinline__ void mma16(float* c, uint32_t a0, uint32_t a1,
                                      uint32_t a2, uint32_t a3,
                                      uint32_t b0, uint32_t b1) {
    asm volatile(
        "mma.sync.aligned.m16n8k16.row.col.f32.f16.f16.f32 "
        "{%0,%1,%2,%3}, {%4,%5,%6,%7}, {%8,%9}, {%0,%1,%2,%3};"
        : "+f"(c[0]), "+f"(c[1]), "+f"(c[2]), "+f"(c[3])
        : "r"(a0), "r"(a1), "r"(a2), "r"(a3), "r"(b0), "r"(b1));
}
__device__ __forceinline__ float softplus_f(float v) {
    return fmaxf(v, 0.f) + __logf(1.f + __expf(-fabsf(v)));
}
__device__ __forceinline__ int hpos(int k) {
    int rel = k & 31;
    return ((k >> 5) << 5) + (((rel >> 1) & 3) << 3) + ((rel >> 3) << 1) + (rel & 1);
}

// ---------------------------------------------------------------------------
// prep: pack weights to fp16 (R9-verified column map).
// ---------------------------------------------------------------------------
__global__ void prep_weights(const float* __restrict__ W1, const float* __restrict__ W2,
                             const float* __restrict__ W3, const float* __restrict__ W4)
{
    int idx = blockIdx.x * blockDim.x + threadIdx.x;
    if (idx >= WPK_TOT) return;
    float v;
    if (idx < WPK_W2) {                               // W1: 128 x 32 halves
        int n = idx >> 5, p = idx & 31;
        int mm = p >> 3, hh = p & 7;
        int k = 2 * mm + (hh & 1) + 8 * (hh >> 1);
        v = W1[n * 32 + k];
    } else if (idx < WPK_W4) {                        // W2/W3: k0,k1 [128][64]
        int t = idx - WPK_W2;
        const float* W = (t < 16384) ? W2 : W3;
        int r = t & 16383;
        int kh = r >> 13, rr = r & 8191;
        int n = rr >> 6, p = rr & 63;
        int kg = p >> 5, rem = p & 31, mm = rem >> 3, hh = rem & 7;
        int kl = kg * 32 + 2 * mm + (hh & 1) + 8 * (hh >> 1);
        v = W[n * 128 + kh * 64 + kl];
    } else {                                          // W4: 8 x (k0,k1) [104][64]
        int t = idx - WPK_W4;
        int c = t / W4_CH, r = t - c * W4_CH;
        int kh = (r >= 6656) ? 1 : 0;
        int rr = kh ? r - 6656 : r;
        int n = rr >> 6, p = rr & 63;
        int kg = p >> 5, rem = p & 31, mm = rem >> 3, hh = rem & 7;
        int kl = kg * 32 + 2 * mm + (hh & 1) + 8 * (hh >> 1);
        v = (n < 100) ? W4[(size_t)(c * 100 + n) * 128 + kh * 64 + kl] : 0.f;
    }
    g_wpk[idx] = __float2half_rn(v);
}

// ---------------------------------------------------------------------------
template<int ROWH>
__device__ __forceinline__ void stage_u(__half* dst, const __half* src, int nrows) {
    constexpr int CH = ROWH / 8;
    for (int i = threadIdx.x; i < nrows * CH; i += THREADS) {
        int row = i / CH, j = i - row * CH;
        cp16(dst + row * SW_H + j * 8, src + row * ROWH + j * 8);
    }
}

// MMA over one staged k-half unit; 2 m-tiles, NT n-tiles per warp.
template<int NT, int KG>
__device__ __forceinline__ void mma_unit2(const __half* a0p, const __half* a1p,
                                          const __half* Wg, float* C) {
    #pragma unroll
    for (int kg = 0; kg < KG; kg++) {
        uint4 X0 = *(const uint4*)(a0p + kg * 32);
        uint4 Y0 = *(const uint4*)(a0p + 8 * SA_H + kg * 32);
        uint4 X1 = *(const uint4*)(a1p + kg * 32);
        uint4 Y1 = *(const uint4*)(a1p + 8 * SA_H + kg * 32);
        #pragma unroll
        for (int nt = 0; nt < NT; nt++) {
            uint4 Wv = *(const uint4*)(Wg + nt * 8 * SW_H + kg * 32);
            mma16(C + nt * 8,     X0.x, Y0.x, X0.y, Y0.y, Wv.x, Wv.y);
            mma16(C + nt * 8,     X0.z, Y0.z, X0.w, Y0.w, Wv.z, Wv.w);
            mma16(C + nt * 8 + 4, X1.x, Y1.x, X1.y, Y1.y, Wv.x, Wv.y);
            mma16(C + nt * 8 + 4, X1.z, Y1.z, X1.w, Y1.w, Wv.z, Wv.w);
        }
    }
}

// relu(C + bias) -> packed fp16 A (own 32 rows x own 32-col group)
__device__ __forceinline__ void relu_store2(const float* C, const float* bs,
                                            __half* Ah, int R0, int ng) {
    const int lane = threadIdx.x & 31;
    const int g = lane >> 2, m = lane & 3;
    #pragma unroll
    for (int mt = 0; mt < 2; mt++) {
        const int rb = R0 + mt * 16;
        #pragma unroll
        for (int nt = 0; nt < 4; nt++) {
            const int ntg = nt + ng * 4;
            const int c0 = ntg * 8 + 2 * m;
            const float b0 = bs[c0], b1 = bs[c0 + 1];
            const int off = ((ntg >> 2) << 5) + (m << 3) + ((ntg & 3) << 1);
            const float* Cc = C + nt * 8 + mt * 4;
            *(__half2*)(Ah + (rb + g) * SA_H + off) =
                __floats2half2_rn(fmaxf(Cc[0] + b0, 0.f), fmaxf(Cc[1] + b1, 0.f));
            *(__half2*)(Ah + (rb + g + 8) * SA_H + off) =
                __floats2half2_rn(fmaxf(Cc[2] + b0, 0.f), fmaxf(Cc[3] + b1, 0.f));
        }
    }
}

// column-major P store: P[col*SRP + row]; tilebase = first n-tile * 8
template<int NT>
__device__ __forceinline__ void p_store2(const float* C, float* P, int R0, int colbase) {
    const int lane = threadIdx.x & 31;
    const int g = lane >> 2, m = lane & 3;
    #pragma unroll
    for (int mt = 0; mt < 2; mt++) {
        const int rb = R0 + mt * 16;
        #pragma unroll
        for (int nt = 0; nt < NT; nt++) {
            const int c0 = colbase + nt * 8 + 2 * m;
            const float* Cc = C + nt * 8 + mt * 4;
            P[c0 * SRP + rb + g]           = Cc[0];
            P[(c0 + 1) * SRP + rb + g]     = Cc[1];
            P[c0 * SRP + rb + g + 8]       = Cc[2];
            P[(c0 + 1) * SRP + rb + g + 8] = Cc[3];
        }
    }
}

// ---------------------------------------------------------------------------
__global__ __launch_bounds__(THREADS, 1)
void rqs_mma_kernel(const float* __restrict__ x,
                    const float* __restrict__ b1, const float* __restrict__ b2,
                    const float* __restrict__ b3, const float* __restrict__ b4,
                    float* __restrict__ out, int B)
{
    extern __shared__ char smem[];
    __half* Ah  = (__half*)(smem + A_B);
    __half* WAb = (__half*)(smem + WA_B);
    __half* WBb = (__half*)(smem + WB_B);
    float*  Psm = (float*)(smem + P_B);
    float*  B1S = (float*)(smem + B1_B);
    float*  B2S = (float*)(smem + B2_B);
    float*  B3S = (float*)(smem + B3_B);
    float*  B4S = (float*)(smem + B4_B);
    float*  LDA = (float*)(smem + LD_B);

    const int tid  = threadIdx.x;
    const int lane = tid & 31;
    const int g    = lane >> 2, m = lane & 3;
    const int warp = tid >> 5;
    const int rg   = warp & 3;            // rowgroup (32 rows)
    const int ng   = warp >> 2;           // n-group (0..3)
    const int R0   = rg * 32;
    const long row0 = (long)blockIdx.x * 128;

    // layer4 tile split {4,3,3,3}: base tile index
    const int tb4  = (ng == 0) ? 0 : (3 * ng + 1);
    const int cb4  = tb4 * 8;             // column base in P

    const __half* aw0 = Ah + (R0 + g) * SA_H + m * 8;
    const __half* aw1 = aw0 + 16 * SA_H;
    const __half* WAg  = WAb + (ng * 32 + g) * SW_H + m * 8;   // layers 1-3
    const __half* WBg  = WBb + (ng * 32 + g) * SW_H + m * 8;
    const __half* WAg4 = WAb + (cb4 + g) * SW_H + m * 8;       // layer 4
    const __half* WBg4 = WBb + (cb4 + g) * SW_H + m * 8;
    const __half* gw = g_wpk;

    // ---- g0: W1 + biases -> WA ; g1: W2k0 -> WB ----
    stage_u<32>(WAb, gw + WPK_W1, 128);
    for (int i = tid; i < 32; i += THREADS) {
        cp16(B1S + i * 4, b1 + i * 4);
        cp16(B2S + i * 4, b2 + i * 4);
        cp16(B3S + i * 4, b3 + i * 4);
    }
    for (int i = tid; i < 200; i += THREADS) cp16(B4S + i * 4, b4 + i * 4);
    cp_commit();
    stage_u<64>(WBb, gw + WPK_W2, 128); cp_commit();

    // ---- x_masked -> packed fp16 A ----
    for (int i = tid; i < 1024; i += THREADS) {
        int row = i >> 3, j = i & 7;
        float4 v = make_float4(0.f, 0.f, 0.f, 0.f);
        if (row0 + row < B) v = *(const float4*)(x + (row0 + row) * 64 + j * 4);
        __half* Ar = Ah + row * SA_H;
        Ar[hpos(j * 4 + 0)] = __float2half_rn(v.x);
        Ar[hpos(j * 4 + 1)] = __float2half_rn(v.y);
        Ar[hpos(j * 4 + 2)] = __float2half_rn(v.z);
        Ar[hpos(j * 4 + 3)] = __float2half_rn(v.w);
    }

    cp_wait<1>(); __syncthreads();

    float C[32];

    // ================= Layer 1 (K=32) =================
    #pragma unroll
    for (int i = 0; i < 32; i++) C[i] = 0.f;
    mma_unit2<4, 1>(aw0, aw1, WAg, C);
    __syncthreads(); stage_u<64>(WAb, gw + WPK_W2 + 8192, 128); cp_commit();   // W2k1
    relu_store2(C, B1S, Ah, R0, ng);                                           // h1

    // ================= Layer 2 =================
    #pragma unroll
    for (int i = 0; i < 32; i++) C[i] = 0.f;
    cp_wait<1>(); __syncthreads();
    mma_unit2<4, 2>(aw0, aw1, WBg, C);                                         // k0
    __syncthreads(); stage_u<64>(WBb, gw + WPK_W3, 128); cp_commit();          // W3k0
    cp_wait<1>(); __syncthreads();
    mma_unit2<4, 2>(aw0 + 64, aw1 + 64, WAg, C);                               // k1
    __syncthreads(); stage_u<64>(WAb, gw + WPK_W3 + 8192, 128); cp_commit();   // W3k1
    relu_store2(C, B2S, Ah, R0, ng);                                           // h2

    // ================= Layer 3 =================
    #pragma unroll
    for (int i = 0; i < 32; i++) C[i] = 0.f;
    cp_wait<1>(); __syncthreads();
    mma_unit2<4, 2>(aw0, aw1, WBg, C);
    __syncthreads(); stage_u<64>(WBb, gw + WPK_W4, 104); cp_commit();          // c0 k0
    cp_wait<1>(); __syncthreads();
    mma_unit2<4, 2>(aw0 + 64, aw1 + 64, WAg, C);
    __syncthreads(); stage_u<64>(WAb, gw + WPK_W4 + 6656, 104); cp_commit();   // c0 k1
    relu_store2(C, B3S, Ah, R0, ng);                                           // h3

    // ================= Layer 4 + spline, 8 chunks =================
    const float MINB = 1e-4f;
    const float FREE = 10.f - 8.f * 1e-4f;
    // epilogue task (fixed across chunks): dim q, row erow
    const int q    = warp & 3;
    const int erow = (warp >> 2) * 32 + lane;
    float ldsum = 0.f;

    #pragma unroll 1
    for (int c = 0; c < 8; c++) {
        const __half* nk = gw + WPK_W4 + (c + 1) * W4_CH;

        #pragma unroll
        for (int i = 0; i < 32; i++) C[i] = 0.f;

        cp_wait<1>(); __syncthreads();                 // k0 in WB; prev P reads done
        if (ng == 0) mma_unit2<4, 2>(aw0, aw1, WBg4, C);
        else         mma_unit2<3, 2>(aw0, aw1, WBg4, C);
        __syncthreads();
        if (c < 7) { stage_u<64>(WBb, nk, 104); cp_commit(); }          // next k0
        if (c < 7) { cp_wait<1>(); } else { cp_wait<0>(); }
        __syncthreads();                               // k1 in WA
        if (ng == 0) mma_unit2<4, 2>(aw0 + 64, aw1 + 64, WAg4, C);
        else         mma_unit2<3, 2>(aw0 + 64, aw1 + 64, WAg4, C);
        __syncthreads();
        if (c < 7) { stage_u<64>(WAb, nk + 6656, 104); cp_commit(); }   // next k1
        if (ng == 0) p_store2<4>(C, Psm, R0, cb4);
        else         p_store2<3>(C, Psm, R0, cb4);
        __syncthreads();

        // -------- spline epilogue: 1 task/thread --------
        {
            const int t = c * 4 + q;

            float acc[25];
            #pragma unroll
            for (int p = 0; p < 25; p++)
                acc[p] = Psm[(q * 25 + p) * SRP + erow] + B4S[c * 100 + q * 25 + p];

            float mx = acc[0];
            #pragma unroll
            for (int i = 1; i < 8; i++) mx = fmaxf(mx, acc[i]);
            float wdt[8]; float Sw = 0.f;
            #pragma unroll
            for (int i = 0; i < 8; i++) { wdt[i] = __expf(acc[i] - mx); Sw += wdt[i]; }
            float mh = acc[8];
            #pragma unroll
            for (int i = 9; i < 16; i++) mh = fmaxf(mh, acc[i]);
            float hgt[8]; float Sh = 0.f;
            #pragma unroll
            for (int i = 0; i < 8; i++) { hgt[i] = __expf(acc[8 + i] - mh); Sh += hgt[i]; }
            const float fw = FREE / Sw, fh = FREE / Sh;
            #pragma unroll
            for (int i = 0; i < 8; i++) {
                wdt[i] = MINB + wdt[i] * fw;
                hgt[i] = MINB + hgt[i] * fh;
            }

            float xt = 0.f;
            const bool vr = (row0 + erow) < B;
            if (vr) xt = x[(row0 + erow) * 64 + 32 + t];
            const float xc = fminf(fmaxf(xt, -5.f), 5.f);
            const bool inside = (xt >= -5.f) && (xt <= 5.f);

            int idx = 0; float cum = -5.f, xk = -5.f, wk = wdt[0];
            #pragma unroll
            for (int i = 0; i < 7; i++) {
                cum += wdt[i];
                if (xc >= cum) { idx = i + 1; xk = cum; wk = wdt[i + 1]; }
            }
            float cumh = -5.f, yk = -5.f, hk = hgt[0];
            #pragma unroll
            for (int i = 0; i < 7; i++) {
                cumh += hgt[i];
                if (idx > i) { yk = cumh; hk = hgt[i + 1]; }
            }
            float sA = acc[16], sB = acc[17];
            #pragma unroll
            for (int i = 1; i < 8; i++)
                if (idx >= i) { sA = acc[16 + i]; sB = acc[17 + i]; }
            const float dk  = 1e-4f + softplus_f(sA);
            const float dk1 = 1e-4f + softplus_f(sB);

            const float rwk  = 1.f / wk;
            const float xi   = (xc - xk) * rwk;
            const float om   = 1.f - xi;
            const float sk   = hk * rwk;
            const float xiom = xi * om;
            const float den  = sk + (dk1 + dk - 2.f * sk) * xiom;
            const float rden = 1.f / den;
            const float num  = sk * xi * xi + dk * xiom;
            const float y_in = yk + hk * num * rden;
            const float num2 = dk1 * xi * xi + 2.f * sk * xiom + dk * om * om;
            const float ld_in = __logf(sk * sk * num2 * rden * rden);

            if (vr) out[(row0 + erow) * 64 + 32 + t] = inside ? y_in : xt;
            ldsum += inside ? ld_in : 0.f;
        }
    }

    // ---- logdet: 4 dim-partials per row via smem ----
    LDA[q * 128 + erow] = ldsum;
    __syncthreads();
    if (tid < 128) {
        float v = LDA[tid] + LDA[128 + tid] + LDA[256 + tid] + LDA[384 + tid];
        if (row0 + tid < B) out[(size_t)B * 64 + row0 + tid] = v;
    }

    // ---- masked-column copy ----
    for (int i = tid; i < 1024; i += THREADS) {
        int row = i >> 3, j = i & 7;
        if (row0 + row < B)
            *(float4*)(out + (row0 + row) * 64 + j * 4) =
                *(const float4*)(x + (row0 + row) * 64 + j * 4);
    }
}

// ---------------------------------------------------------------------------
extern "C" void kernel_launch(void* const* d_in, const int* in_sizes, int n_in,
                              void* d_out, int out_size)
{
    const float* x  = (const float*)d_in[0];
    const float* W1 = (const float*)d_in[1];
    const float* b1 = (const float*)d_in[2];
    const float* W2 = (const float*)d_in[3];
    const float* b2 = (const float*)d_in[4];
    const float* W3 = (const float*)d_in[5];
    const float* b3 = (const float*)d_in[6];
    const float* W4 = (const float*)d_in[7];
    const float* b4 = (const float*)d_in[8];
    float* out = (float*)d_out;

    const int B = in_sizes[0] / 64;

    prep_weights<<<(WPK_TOT + 255) / 256, 256>>>(W1, W2, W3, W4);

    cudaFuncSetAttribute(rqs_mma_kernel,
                         cudaFuncAttributeMaxDynamicSharedMemorySize, SMEM_BYTES);
    const int grid = (B + 127) / 128;
    rqs_mma_kernel<<<grid, THREADS, SMEM_BYTES>>>(x, b1, b2, b3, b4, out, B);
}

// round 13
// speedup vs baseline: 1.1422x; 1.0278x over previous
#include <cuda_runtime.h>
#include <cuda_fp16.h>
#include <cstdint>

// ===========================================================================
// MaskedCouplingRQS — Round 13: R12 minus the entire smem weight-staging
// pipeline. W fragments are LDG.128'd straight from the packed g_wpk layout
// (L1-cached, L2-resident); A stays in smem. ~35k LDGSTS and ~20 barriers
// per CTA deleted. Numerics identical to R12.
// ===========================================================================

#define THREADS 512
#define SA_H 160
#define SRP  132

// ---- smem byte offsets ----
#define A_B    0                      // 128*160*2 = 40960
#define P_B    40960                  // 104*132*4 = 54912
#define B1_B   95872
#define B2_B   96384
#define B3_B   96896
#define B4_B   97408                  // 800*4
#define LD_B   100608                 // 512*4
#define SMEM_BYTES 102656

// ---- packed fp16 weights (mma-native fragment order; R9-verified map) ----
#define WPK_W1 0                      // [128][32]
#define WPK_W2 4096                   // k0 [128][64], k1 [128][64]
#define WPK_W3 20480
#define WPK_W4 36864                  // 8 x (k0 [104][64], k1 [104][64])
#define W4_CH  13312
#define WPK_TOT 143360
__device__ __half g_wpk[WPK_TOT];

// --------------------------- helpers ---------------------------------------
__device__ __forceinline__ void mma16(float* c, uint32_t a0, uint32_t a1,
                                      uint32_t a2, uint32_t a3,
                                      uint32_t b0, uint32_t b1) {
    asm volatile(
        "mma.sync.aligned.m16n8k16.row.col.f32.f16.f16.f32 "
        "{%0,%1,%2,%3}, {%4,%5,%6,%7}, {%8,%9}, {%0,%1,%2,%3};"
        : "+f"(c[0]), "+f"(c[1]), "+f"(c[2]), "+f"(c[3])
        : "r"(a0), "r"(a1), "r"(a2), "r"(a3), "r"(b0), "r"(b1));
}
__device__ __forceinline__ float softplus_f(float v) {
    return fmaxf(v, 0.f) + __logf(1.f + __expf(-fabsf(v)));
}
__device__ __forceinline__ int hpos(int k) {
    int rel = k & 31;
    return ((k >> 5) << 5) + (((rel >> 1) & 3) << 3) + ((rel >> 3) << 1) + (rel & 1);
}

// ---------------------------------------------------------------------------
// prep: pack weights to fp16 (identical to R12 — canary-protected).
// ---------------------------------------------------------------------------
__global__ void prep_weights(const float* __restrict__ W1, const float* __restrict__ W2,
                             const float* __restrict__ W3, const float* __restrict__ W4)
{
    int idx = blockIdx.x * blockDim.x + threadIdx.x;
    if (idx >= WPK_TOT) return;
    float v;
    if (idx < WPK_W2) {                               // W1: 128 x 32 halves
        int n = idx >> 5, p = idx & 31;
        int mm = p >> 3, hh = p & 7;
        int k = 2 * mm + (hh & 1) + 8 * (hh >> 1);
        v = W1[n * 32 + k];
    } else if (idx < WPK_W4) {                        // W2/W3: k0,k1 [128][64]
        int t = idx - WPK_W2;
        const float* W = (t < 16384) ? W2 : W3;
        int r = t & 16383;
        int kh = r >> 13, rr = r & 8191;
        int n = rr >> 6, p = rr & 63;
        int kg = p >> 5, rem = p & 31, mm = rem >> 3, hh = rem & 7;
        int kl = kg * 32 + 2 * mm + (hh & 1) + 8 * (hh >> 1);
        v = W[n * 128 + kh * 64 + kl];
    } else {                                          // W4: 8 x (k0,k1) [104][64]
        int t = idx - WPK_W4;
        int c = t / W4_CH, r = t - c * W4_CH;
        int kh = (r >= 6656) ? 1 : 0;
        int rr = kh ? r - 6656 : r;
        int n = rr >> 6, p = rr & 63;
        int kg = p >> 5, rem = p & 31, mm = rem >> 3, hh = rem & 7;
        int kl = kg * 32 + 2 * mm + (hh & 1) + 8 * (hh >> 1);
        v = (n < 100) ? W4[(size_t)(c * 100 + n) * 128 + kh * 64 + kl] : 0.f;
    }
    g_wpk[idx] = __float2half_rn(v);
}

// ---------------------------------------------------------------------------
// MMA over one k-half unit: A from smem (LDS.128), W direct from global
// (LDG.128, packed layout, row stride RS halves). 2 m-tiles, NT n-tiles.
template<int NT, int KG, int RS>
__device__ __forceinline__ void mma_ldg(const __half* a0p, const __half* a1p,
                                        const __half* __restrict__ wg, float* C) {
    #pragma unroll
    for (int kg = 0; kg < KG; kg++) {
        uint4 X0 = *(const uint4*)(a0p + kg * 32);
        uint4 Y0 = *(const uint4*)(a0p + 8 * SA_H + kg * 32);
        uint4 X1 = *(const uint4*)(a1p + kg * 32);
        uint4 Y1 = *(const uint4*)(a1p + 8 * SA_H + kg * 32);
        #pragma unroll
        for (int nt = 0; nt < NT; nt++) {
            uint4 Wv = __ldg((const uint4*)(wg + nt * 8 * RS + kg * 32));
            mma16(C + nt * 8,     X0.x, Y0.x, X0.y, Y0.y, Wv.x, Wv.y);
            mma16(C + nt * 8,     X0.z, Y0.z, X0.w, Y0.w, Wv.z, Wv.w);
            mma16(C + nt * 8 + 4, X1.x, Y1.x, X1.y, Y1.y, Wv.x, Wv.y);
            mma16(C + nt * 8 + 4, X1.z, Y1.z, X1.w, Y1.w, Wv.z, Wv.w);
        }
    }
}

// relu(C + bias) -> packed fp16 A (own 32 rows x own 32-col group)
__device__ __forceinline__ void relu_store2(const float* C, const float* bs,
                                            __half* Ah, int R0, int ng) {
    const int lane = threadIdx.x & 31;
    const int g = lane >> 2, m = lane & 3;
    #pragma unroll
    for (int mt = 0; mt < 2; mt++) {
        const int rb = R0 + mt * 16;
        #pragma unroll
        for (int nt = 0; nt < 4; nt++) {
            const int ntg = nt + ng * 4;
            const int c0 = ntg * 8 + 2 * m;
            const float b0 = bs[c0], b1 = bs[c0 + 1];
            const int off = ((ntg >> 2) << 5) + (m << 3) + ((ntg & 3) << 1);
            const float* Cc = C + nt * 8 + mt * 4;
            *(__half2*)(Ah + (rb + g) * SA_H + off) =
                __floats2half2_rn(fmaxf(Cc[0] + b0, 0.f), fmaxf(Cc[1] + b1, 0.f));
            *(__half2*)(Ah + (rb + g + 8) * SA_H + off) =
                __floats2half2_rn(fmaxf(Cc[2] + b0, 0.f), fmaxf(Cc[3] + b1, 0.f));
        }
    }
}

// column-major P store: P[col*SRP + row]
template<int NT>
__device__ __forceinline__ void p_store2(const float* C, float* P, int R0, int colbase) {
    const int lane = threadIdx.x & 31;
    const int g = lane >> 2, m = lane & 3;
    #pragma unroll
    for (int mt = 0; mt < 2; mt++) {
        const int rb = R0 + mt * 16;
        #pragma unroll
        for (int nt = 0; nt < NT; nt++) {
            const int c0 = colbase + nt * 8 + 2 * m;
            const float* Cc = C + nt * 8 + mt * 4;
            P[c0 * SRP + rb + g]           = Cc[0];
            P[(c0 + 1) * SRP + rb + g]     = Cc[1];
            P[c0 * SRP + rb + g + 8]       = Cc[2];
            P[(c0 + 1) * SRP + rb + g + 8] = Cc[3];
        }
    }
}

// ---------------------------------------------------------------------------
__global__ __launch_bounds__(THREADS, 1)
void rqs_mma_kernel(const float* __restrict__ x,
                    const float* __restrict__ b1, const float* __restrict__ b2,
                    const float* __restrict__ b3, const float* __restrict__ b4,
                    float* __restrict__ out, int B)
{
    extern __shared__ char smem[];
    __half* Ah  = (__half*)(smem + A_B);
    float*  Psm = (float*)(smem + P_B);
    float*  B1S = (float*)(smem + B1_B);
    float*  B2S = (float*)(smem + B2_B);
    float*  B3S = (float*)(smem + B3_B);
    float*  B4S = (float*)(smem + B4_B);
    float*  LDA = (float*)(smem + LD_B);

    const int tid  = threadIdx.x;
    const int lane = tid & 31;
    const int g    = lane >> 2, m = lane & 3;
    const int warp = tid >> 5;
    const int rg   = warp & 3;            // rowgroup (32 rows)
    const int ng   = warp >> 2;           // n-group (0..3)
    const int R0   = rg * 32;
    const long row0 = (long)blockIdx.x * 128;

    // layer4 tile split {4,3,3,3}
    const int tb4 = (ng == 0) ? 0 : (3 * ng + 1);
    const int cb4 = tb4 * 8;

    const __half* aw0 = Ah + (R0 + g) * SA_H + m * 8;
    const __half* aw1 = aw0 + 16 * SA_H;
    const __half* gw  = g_wpk;

    // per-warp global W fragment bases (halves)
    const __half* w1g  = gw + WPK_W1 + (ng * 32 + g) * 32 + m * 8;
    const __half* w2g0 = gw + WPK_W2          + (ng * 32 + g) * 64 + m * 8;
    const __half* w2g1 = gw + WPK_W2 + 8192   + (ng * 32 + g) * 64 + m * 8;
    const __half* w3g0 = gw + WPK_W3          + (ng * 32 + g) * 64 + m * 8;
    const __half* w3g1 = gw + WPK_W3 + 8192   + (ng * 32 + g) * 64 + m * 8;
    const __half* w4gb = gw + WPK_W4 + (cb4 + g) * 64 + m * 8;

    // ---- prologue: x_masked -> packed fp16 A ; biases -> smem ----
    for (int i = tid; i < 1024; i += THREADS) {
        int row = i >> 3, j = i & 7;
        float4 v = make_float4(0.f, 0.f, 0.f, 0.f);
        if (row0 + row < B) v = *(const float4*)(x + (row0 + row) * 64 + j * 4);
        __half* Ar = Ah + row * SA_H;
        Ar[hpos(j * 4 + 0)] = __float2half_rn(v.x);
        Ar[hpos(j * 4 + 1)] = __float2half_rn(v.y);
        Ar[hpos(j * 4 + 2)] = __float2half_rn(v.z);
        Ar[hpos(j * 4 + 3)] = __float2half_rn(v.w);
    }
    if (tid < 128) {
        B1S[tid] = b1[tid];
        B2S[tid] = b2[tid];
        B3S[tid] = b3[tid];
    }
    for (int i = tid; i < 800; i += THREADS) B4S[i] = b4[i];
    __syncthreads();

    float C[32];

    // ================= Layer 1 (K=32) =================
    #pragma unroll
    for (int i = 0; i < 32; i++) C[i] = 0.f;
    mma_ldg<4, 1, 32>(aw0, aw1, w1g, C);
    __syncthreads();
    relu_store2(C, B1S, Ah, R0, ng);                   // h1
    __syncthreads();

    // ================= Layer 2 =================
    #pragma unroll
    for (int i = 0; i < 32; i++) C[i] = 0.f;
    mma_ldg<4, 2, 64>(aw0,      aw1,      w2g0, C);    // k0
    mma_ldg<4, 2, 64>(aw0 + 64, aw1 + 64, w2g1, C);    // k1
    __syncthreads();
    relu_store2(C, B2S, Ah, R0, ng);                   // h2
    __syncthreads();

    // ================= Layer 3 =================
    #pragma unroll
    for (int i = 0; i < 32; i++) C[i] = 0.f;
    mma_ldg<4, 2, 64>(aw0,      aw1,      w3g0, C);
    mma_ldg<4, 2, 64>(aw0 + 64, aw1 + 64, w3g1, C);
    __syncthreads();
    relu_store2(C, B3S, Ah, R0, ng);                   // h3
    __syncthreads();

    // ================= Layer 4 + spline, 8 chunks =================
    const float MINB = 1e-4f;
    const float FREE = 10.f - 8.f * 1e-4f;
    const int q    = warp & 3;                         // epilogue dim
    const int erow = (warp >> 2) * 32 + lane;          // epilogue row
    float ldsum = 0.f;

    #pragma unroll 1
    for (int c = 0; c < 8; c++) {
        const __half* wk0 = w4gb + c * W4_CH;
        const __half* wk1 = wk0 + 6656;

        #pragma unroll
        for (int i = 0; i < 32; i++) C[i] = 0.f;

        if (ng == 0) {
            mma_ldg<4, 2, 64>(aw0,      aw1,      wk0, C);
            mma_ldg<4, 2, 64>(aw0 + 64, aw1 + 64, wk1, C);
        } else {
            mma_ldg<3, 2, 64>(aw0,      aw1,      wk0, C);
            mma_ldg<3, 2, 64>(aw0 + 64, aw1 + 64, wk1, C);
        }
        __syncthreads();                               // prior epilogue P reads done
        if (ng == 0) p_store2<4>(C, Psm, R0, cb4);
        else         p_store2<3>(C, Psm, R0, cb4);
        __syncthreads();

        // -------- spline epilogue: 1 task/thread --------
        {
            const int t = c * 4 + q;

            float acc[25];
            #pragma unroll
            for (int p = 0; p < 25; p++)
                acc[p] = Psm[(q * 25 + p) * SRP + erow] + B4S[c * 100 + q * 25 + p];

            float mx = acc[0];
            #pragma unroll
            for (int i = 1; i < 8; i++) mx = fmaxf(mx, acc[i]);
            float wdt[8]; float Sw = 0.f;
            #pragma unroll
            for (int i = 0; i < 8; i++) { wdt[i] = __expf(acc[i] - mx); Sw += wdt[i]; }
            float mh = acc[8];
            #pragma unroll
            for (int i = 9; i < 16; i++) mh = fmaxf(mh, acc[i]);
            float hgt[8]; float Sh = 0.f;
            #pragma unroll
            for (int i = 0; i < 8; i++) { hgt[i] = __expf(acc[8 + i] - mh); Sh += hgt[i]; }
            const float fw = FREE / Sw, fh = FREE / Sh;
            #pragma unroll
            for (int i = 0; i < 8; i++) {
                wdt[i] = MINB + wdt[i] * fw;
                hgt[i] = MINB + hgt[i] * fh;
            }

            float xt = 0.f;
            const bool vr = (row0 + erow) < B;
            if (vr) xt = x[(row0 + erow) * 64 + 32 + t];
            const float xc = fminf(fmaxf(xt, -5.f), 5.f);
            const bool inside = (xt >= -5.f) && (xt <= 5.f);

            int idx = 0; float cum = -5.f, xk = -5.f, wk = wdt[0];
            #pragma unroll
            for (int i = 0; i < 7; i++) {
                cum += wdt[i];
                if (xc >= cum) { idx = i + 1; xk = cum; wk = wdt[i + 1]; }
            }
            float cumh = -5.f, yk = -5.f, hk = hgt[0];
            #pragma unroll
            for (int i = 0; i < 7; i++) {
                cumh += hgt[i];
                if (idx > i) { yk = cumh; hk = hgt[i + 1]; }
            }
            float sA = acc[16], sB = acc[17];
            #pragma unroll
            for (int i = 1; i < 8; i++)
                if (idx >= i) { sA = acc[16 + i]; sB = acc[17 + i]; }
            const float dk  = 1e-4f + softplus_f(sA);
            const float dk1 = 1e-4f + softplus_f(sB);

            const float rwk  = 1.f / wk;
            const float xi   = (xc - xk) * rwk;
            const float om   = 1.f - xi;
            const float sk   = hk * rwk;
            const float xiom = xi * om;
            const float den  = sk + (dk1 + dk - 2.f * sk) * xiom;
            const float rden = 1.f / den;
            const float num  = sk * xi * xi + dk * xiom;
            const float y_in = yk + hk * num * rden;
            const float num2 = dk1 * xi * xi + 2.f * sk * xiom + dk * om * om;
            const float ld_in = __logf(sk * sk * num2 * rden * rden);

            if (vr) out[(row0 + erow) * 64 + 32 + t] = inside ? y_in : xt;
            ldsum += inside ? ld_in : 0.f;
        }
    }

    // ---- logdet: 4 dim-partials per row via smem ----
    LDA[q * 128 + erow] = ldsum;
    __syncthreads();
    if (tid < 128) {
        float v = LDA[tid] + LDA[128 + tid] + LDA[256 + tid] + LDA[384 + tid];
        if (row0 + tid < B) out[(size_t)B * 64 + row0 + tid] = v;
    }

    // ---- masked-column copy ----
    for (int i = tid; i < 1024; i += THREADS) {
        int row = i >> 3, j = i & 7;
        if (row0 + row < B)
            *(float4*)(out + (row0 + row) * 64 + j * 4) =
                *(const float4*)(x + (row0 + row) * 64 + j * 4);
    }
}

// ---------------------------------------------------------------------------
extern "C" void kernel_launch(void* const* d_in, const int* in_sizes, int n_in,
                              void* d_out, int out_size)
{
    const float* x  = (const float*)d_in[0];
    const float* W1 = (const float*)d_in[1];
    const float* b1 = (const float*)d_in[2];
    const float* W2 = (const float*)d_in[3];
    const float* b2 = (const float*)d_in[4];
    const float* W3 = (const float*)d_in[5];
    const float* b3 = (const float*)d_in[6];
    const float* W4 = (const float*)d_in[7];
    const float* b4 = (const float*)d_in[8];
    float* out = (float*)d_out;

    const int B = in_sizes[0] / 64;

    prep_weights<<<(WPK_TOT + 255) / 256, 256>>>(W1, W2, W3, W4);

    cudaFuncSetAttribute(rqs_mma_kernel,
                         cudaFuncAttributeMaxDynamicSharedMemorySize, SMEM_BYTES);
    const int grid = (B + 127) / 128;
    rqs_mma_kernel<<<grid, THREADS, SMEM_BYTES>>>(x, b1, b2, b3, b4, out, B);
}

// round 14
// speedup vs baseline: 1.2251x; 1.0726x over previous
#include <cuda_runtime.h>
#include <cuda_fp16.h>
#include <cstdint>

// ===========================================================================
// MaskedCouplingRQS — Round 14: R13 with W repacked into contiguous 512B
// fragments (one LDG.128 per fragment = 4 coalesced lines, was 8 scattered).
// Values and accumulation order identical to R13 (canary rel_err 4.5069e-4).
// ===========================================================================

#define THREADS 512
#define SA_H 160
#define SRP  132

// ---- smem byte offsets ----
#define A_B    0                      // 128*160*2 = 40960
#define P_B    40960                  // 104*132*4 = 54912
#define B1_B   95872
#define B2_B   96384
#define B3_B   96896
#define B4_B   97408                  // 800*4
#define LD_B   100608                 // 512*4
#define SMEM_BYTES 102656

// ---- packed fp16 weights: contiguous 256-half fragments ----
// fragment (ntile, kg) of a unit sits at (ntile*NKG + kg)*256; lane l owns
// halves [l*8, l*8+8) = old (row ntile*8 + (l>>2), packed col kg*32+(l&3)*8..)
#define WPK_W1 0                      // 16 frags (NKG=1)
#define WPK_W2 4096                   // k0: 32 frags, k1: 32 frags (NKG=2)
#define WPK_W3 20480
#define WPK_W4 36864                  // 8 x (k0: 26 frags, k1: 26 frags)
#define W4_CH  13312
#define WPK_TOT 143360
__device__ __half g_wpk[WPK_TOT];

// --------------------------- helpers ---------------------------------------
__device__ __forceinline__ void mma16(float* c, uint32_t a0, uint32_t a1,
                                      uint32_t a2, uint32_t a3,
                                      uint32_t b0, uint32_t b1) {
    asm volatile(
        "mma.sync.aligned.m16n8k16.row.col.f32.f16.f16.f32 "
        "{%0,%1,%2,%3}, {%4,%5,%6,%7}, {%8,%9}, {%0,%1,%2,%3};"
        : "+f"(c[0]), "+f"(c[1]), "+f"(c[2]), "+f"(c[3])
        : "r"(a0), "r"(a1), "r"(a2), "r"(a3), "r"(b0), "r"(b1));
}
__device__ __forceinline__ float softplus_f(float v) {
    return fmaxf(v, 0.f) + __logf(1.f + __expf(-fabsf(v)));
}
__device__ __forceinline__ int hpos(int k) {
    int rel = k & 31;
    return ((k >> 5) << 5) + (((rel >> 1) & 3) << 3) + ((rel >> 3) << 1) + (rel & 1);
}

// ---------------------------------------------------------------------------
// prep: pack weights to fp16 in contiguous-fragment order.
// Decompose fragment element: lane = e>>3, h8 = e&7 ->
//   row-in-unit = ntile*8 + (lane>>2); mm = lane&3; hh = h8;
//   k-in-kgroup = 2*mm + (hh&1) + 8*(hh>>1)   (same value map as R13)
// ---------------------------------------------------------------------------
__global__ void prep_weights(const float* __restrict__ W1, const float* __restrict__ W2,
                             const float* __restrict__ W3, const float* __restrict__ W4)
{
    int idx = blockIdx.x * blockDim.x + threadIdx.x;
    if (idx >= WPK_TOT) return;
    float v;
    if (idx < WPK_W2) {                               // W1: 16 frags, NKG=1
        int f = idx >> 8, e = idx & 255;
        int lane = e >> 3, h8 = e & 7;
        int n = f * 8 + (lane >> 2);
        int mm = lane & 3;
        int k = 2 * mm + (h8 & 1) + 8 * (h8 >> 1);
        v = W1[n * 32 + k];
    } else if (idx < WPK_W4) {                        // W2/W3: k0,k1; NKG=2
        int t = idx - WPK_W2;
        const float* W = (t < 16384) ? W2 : W3;
        int r = t & 16383;
        int kh = r >> 13, rr = r & 8191;
        int f = rr >> 8, e = rr & 255;
        int lane = e >> 3, h8 = e & 7;
        int ntl = f >> 1, kg = f & 1;
        int n = ntl * 8 + (lane >> 2);
        int mm = lane & 3;
        int kl = kg * 32 + 2 * mm + (h8 & 1) + 8 * (h8 >> 1);
        v = W[n * 128 + kh * 64 + kl];
    } else {                                          // W4: 8 x (k0,k1); NKG=2
        int t = idx - WPK_W4;
        int c = t / W4_CH, r = t - c * W4_CH;
        int kh = (r >= 6656) ? 1 : 0;
        int rr = kh ? r - 6656 : r;
        int f = rr >> 8, e = rr & 255;
        int lane = e >> 3, h8 = e & 7;
        int ntl = f >> 1, kg = f & 1;
        int n = ntl * 8 + (lane >> 2);
        int mm = lane & 3;
        int kl = kg * 32 + 2 * mm + (h8 & 1) + 8 * (h8 >> 1);
        v = (n < 100) ? W4[(size_t)(c * 100 + n) * 128 + kh * 64 + kl] : 0.f;
    }
    g_wpk[idx] = __float2half_rn(v);
}

// ---------------------------------------------------------------------------
// MMA over one k-half unit: A from smem (LDS.128), W from global in
// contiguous fragments: frag (nt, kg) at wg + (nt*KG + kg)*256 halves.
template<int NT, int KG>
__device__ __forceinline__ void mma_ldg(const __half* a0p, const __half* a1p,
                                        const __half* __restrict__ wg, float* C) {
    #pragma unroll
    for (int kg = 0; kg < KG; kg++) {
        uint4 X0 = *(const uint4*)(a0p + kg * 32);
        uint4 Y0 = *(const uint4*)(a0p + 8 * SA_H + kg * 32);
        uint4 X1 = *(const uint4*)(a1p + kg * 32);
        uint4 Y1 = *(const uint4*)(a1p + 8 * SA_H + kg * 32);
        #pragma unroll
        for (int nt = 0; nt < NT; nt++) {
            uint4 Wv = __ldg((const uint4*)(wg + (nt * KG + kg) * 256));
            mma16(C + nt * 8,     X0.x, Y0.x, X0.y, Y0.y, Wv.x, Wv.y);
            mma16(C + nt * 8,     X0.z, Y0.z, X0.w, Y0.w, Wv.z, Wv.w);
            mma16(C + nt * 8 + 4, X1.x, Y1.x, X1.y, Y1.y, Wv.x, Wv.y);
            mma16(C + nt * 8 + 4, X1.z, Y1.z, X1.w, Y1.w, Wv.z, Wv.w);
        }
    }
}

// relu(C + bias) -> packed fp16 A (own 32 rows x own 32-col group)
__device__ __forceinline__ void relu_store2(const float* C, const float* bs,
                                            __half* Ah, int R0, int ng) {
    const int lane = threadIdx.x & 31;
    const int g = lane >> 2, m = lane & 3;
    #pragma unroll
    for (int mt = 0; mt < 2; mt++) {
        const int rb = R0 + mt * 16;
        #pragma unroll
        for (int nt = 0; nt < 4; nt++) {
            const int ntg = nt + ng * 4;
            const int c0 = ntg * 8 + 2 * m;
            const float b0 = bs[c0], b1 = bs[c0 + 1];
            const int off = ((ntg >> 2) << 5) + (m << 3) + ((ntg & 3) << 1);
            const float* Cc = C + nt * 8 + mt * 4;
            *(__half2*)(Ah + (rb + g) * SA_H + off) =
                __floats2half2_rn(fmaxf(Cc[0] + b0, 0.f), fmaxf(Cc[1] + b1, 0.f));
            *(__half2*)(Ah + (rb + g + 8) * SA_H + off) =
                __floats2half2_rn(fmaxf(Cc[2] + b0, 0.f), fmaxf(Cc[3] + b1, 0.f));
        }
    }
}

// column-major P store: P[col*SRP + row]
template<int NT>
__device__ __forceinline__ void p_store2(const float* C, float* P, int R0, int colbase) {
    const int lane = threadIdx.x & 31;
    const int g = lane >> 2, m = lane & 3;
    #pragma unroll
    for (int mt = 0; mt < 2; mt++) {
        const int rb = R0 + mt * 16;
        #pragma unroll
        for (int nt = 0; nt < NT; nt++) {
            const int c0 = colbase + nt * 8 + 2 * m;
            const float* Cc = C + nt * 8 + mt * 4;
            P[c0 * SRP + rb + g]           = Cc[0];
            P[(c0 + 1) * SRP + rb + g]     = Cc[1];
            P[c0 * SRP + rb + g + 8]       = Cc[2];
            P[(c0 + 1) * SRP + rb + g + 8] = Cc[3];
        }
    }
}

// ---------------------------------------------------------------------------
__global__ __launch_bounds__(THREADS, 1)
void rqs_mma_kernel(const float* __restrict__ x,
                    const float* __restrict__ b1, const float* __restrict__ b2,
                    const float* __restrict__ b3, const float* __restrict__ b4,
                    float* __restrict__ out, int B)
{
    extern __shared__ char smem[];
    __half* Ah  = (__half*)(smem + A_B);
    float*  Psm = (float*)(smem + P_B);
    float*  B1S = (float*)(smem + B1_B);
    float*  B2S = (float*)(smem + B2_B);
    float*  B3S = (float*)(smem + B3_B);
    float*  B4S = (float*)(smem + B4_B);
    float*  LDA = (float*)(smem + LD_B);

    const int tid  = threadIdx.x;
    const int lane = tid & 31;
    const int g    = lane >> 2, m = lane & 3;
    const int warp = tid >> 5;
    const int rg   = warp & 3;            // rowgroup (32 rows)
    const int ng   = warp >> 2;           // n-group (0..3)
    const int R0   = rg * 32;
    const long row0 = (long)blockIdx.x * 128;

    // layer4 tile split {4,3,3,3}
    const int tb4 = (ng == 0) ? 0 : (3 * ng + 1);
    const int cb4 = tb4 * 8;

    const __half* aw0 = Ah + (R0 + g) * SA_H + m * 8;
    const __half* aw1 = aw0 + 16 * SA_H;
    const __half* gw  = g_wpk;

    // per-warp global W fragment bases (contiguous-fragment layout)
    const __half* w1g  = gw + WPK_W1        + ng * 4 * 256 + lane * 8;  // NKG=1
    const __half* w2g0 = gw + WPK_W2        + ng * 4 * 512 + lane * 8;  // NKG=2
    const __half* w2g1 = gw + WPK_W2 + 8192 + ng * 4 * 512 + lane * 8;
    const __half* w3g0 = gw + WPK_W3        + ng * 4 * 512 + lane * 8;
    const __half* w3g1 = gw + WPK_W3 + 8192 + ng * 4 * 512 + lane * 8;
    const __half* w4gb = gw + WPK_W4        + tb4 * 512    + lane * 8;

    // ---- prologue: x_masked -> packed fp16 A ; biases -> smem ----
    for (int i = tid; i < 1024; i += THREADS) {
        int row = i >> 3, j = i & 7;
        float4 v = make_float4(0.f, 0.f, 0.f, 0.f);
        if (row0 + row < B) v = *(const float4*)(x + (row0 + row) * 64 + j * 4);
        __half* Ar = Ah + row * SA_H;
        Ar[hpos(j * 4 + 0)] = __float2half_rn(v.x);
        Ar[hpos(j * 4 + 1)] = __float2half_rn(v.y);
        Ar[hpos(j * 4 + 2)] = __float2half_rn(v.z);
        Ar[hpos(j * 4 + 3)] = __float2half_rn(v.w);
    }
    if (tid < 128) {
        B1S[tid] = b1[tid];
        B2S[tid] = b2[tid];
        B3S[tid] = b3[tid];
    }
    for (int i = tid; i < 800; i += THREADS) B4S[i] = b4[i];
    __syncthreads();

    float C[32];

    // ================= Layer 1 (K=32) =================
    #pragma unroll
    for (int i = 0; i < 32; i++) C[i] = 0.f;
    mma_ldg<4, 1>(aw0, aw1, w1g, C);
    __syncthreads();
    relu_store2(C, B1S, Ah, R0, ng);                   // h1
    __syncthreads();

    // ================= Layer 2 =================
    #pragma unroll
    for (int i = 0; i < 32; i++) C[i] = 0.f;
    mma_ldg<4, 2>(aw0,      aw1,      w2g0, C);        // k0
    mma_ldg<4, 2>(aw0 + 64, aw1 + 64, w2g1, C);        // k1
    __syncthreads();
    relu_store2(C, B2S, Ah, R0, ng);                   // h2
    __syncthreads();

    // ================= Layer 3 =================
    #pragma unroll
    for (int i = 0; i < 32; i++) C[i] = 0.f;
    mma_ldg<4, 2>(aw0,      aw1,      w3g0, C);
    mma_ldg<4, 2>(aw0 + 64, aw1 + 64, w3g1, C);
    __syncthreads();
    relu_store2(C, B3S, Ah, R0, ng);                   // h3
    __syncthreads();

    // ================= Layer 4 + spline, 8 chunks =================
    const float MINB = 1e-4f;
    const float FREE = 10.f - 8.f * 1e-4f;
    const int q    = warp & 3;                         // epilogue dim
    const int erow = (warp >> 2) * 32 + lane;          // epilogue row
    float ldsum = 0.f;

    #pragma unroll 1
    for (int c = 0; c < 8; c++) {
        const __half* wk0 = w4gb + c * W4_CH;
        const __half* wk1 = wk0 + 6656;

        #pragma unroll
        for (int i = 0; i < 32; i++) C[i] = 0.f;

        if (ng == 0) {
            mma_ldg<4, 2>(aw0,      aw1,      wk0, C);
            mma_ldg<4, 2>(aw0 + 64, aw1 + 64, wk1, C);
        } else {
            mma_ldg<3, 2>(aw0,      aw1,      wk0, C);
            mma_ldg<3, 2>(aw0 + 64, aw1 + 64, wk1, C);
        }
        __syncthreads();                               // prior epilogue P reads done
        if (ng == 0) p_store2<4>(C, Psm, R0, cb4);
        else         p_store2<3>(C, Psm, R0, cb4);
        __syncthreads();

        // -------- spline epilogue: 1 task/thread --------
        {
            const int t = c * 4 + q;

            float acc[25];
            #pragma unroll
            for (int p = 0; p < 25; p++)
                acc[p] = Psm[(q * 25 + p) * SRP + erow] + B4S[c * 100 + q * 25 + p];

            float mx = acc[0];
            #pragma unroll
            for (int i = 1; i < 8; i++) mx = fmaxf(mx, acc[i]);
            float wdt[8]; float Sw = 0.f;
            #pragma unroll
            for (int i = 0; i < 8; i++) { wdt[i] = __expf(acc[i] - mx); Sw += wdt[i]; }
            float mh = acc[8];
            #pragma unroll
            for (int i = 9; i < 16; i++) mh = fmaxf(mh, acc[i]);
            float hgt[8]; float Sh = 0.f;
            #pragma unroll
            for (int i = 0; i < 8; i++) { hgt[i] = __expf(acc[8 + i] - mh); Sh += hgt[i]; }
            const float fw = FREE / Sw, fh = FREE / Sh;
            #pragma unroll
            for (int i = 0; i < 8; i++) {
                wdt[i] = MINB + wdt[i] * fw;
                hgt[i] = MINB + hgt[i] * fh;
            }

            float xt = 0.f;
            const bool vr = (row0 + erow) < B;
            if (vr) xt = x[(row0 + erow) * 64 + 32 + t];
            const float xc = fminf(fmaxf(xt, -5.f), 5.f);
            const bool inside = (xt >= -5.f) && (xt <= 5.f);

            int idx = 0; float cum = -5.f, xk = -5.f, wk = wdt[0];
            #pragma unroll
            for (int i = 0; i < 7; i++) {
                cum += wdt[i];
                if (xc >= cum) { idx = i + 1; xk = cum; wk = wdt[i + 1]; }
            }
            float cumh = -5.f, yk = -5.f, hk = hgt[0];
            #pragma unroll
            for (int i = 0; i < 7; i++) {
                cumh += hgt[i];
                if (idx > i) { yk = cumh; hk = hgt[i + 1]; }
            }
            float sA = acc[16], sB = acc[17];
            #pragma unroll
            for (int i = 1; i < 8; i++)
                if (idx >= i) { sA = acc[16 + i]; sB = acc[17 + i]; }
            const float dk  = 1e-4f + softplus_f(sA);
            const float dk1 = 1e-4f + softplus_f(sB);

            const float rwk  = 1.f / wk;
            const float xi   = (xc - xk) * rwk;
            const float om   = 1.f - xi;
            const float sk   = hk * rwk;
            const float xiom = xi * om;
            const float den  = sk + (dk1 + dk - 2.f * sk) * xiom;
            const float rden = 1.f / den;
            const float num  = sk * xi * xi + dk * xiom;
            const float y_in = yk + hk * num * rden;
            const float num2 = dk1 * xi * xi + 2.f * sk * xiom + dk * om * om;
            const float ld_in = __logf(sk * sk * num2 * rden * rden);

            if (vr) out[(row0 + erow) * 64 + 32 + t] = inside ? y_in : xt;
            ldsum += inside ? ld_in : 0.f;
        }
    }

    // ---- logdet: 4 dim-partials per row via smem ----
    LDA[q * 128 + erow] = ldsum;
    __syncthreads();
    if (tid < 128) {
        float v = LDA[tid] + LDA[128 + tid] + LDA[256 + tid] + LDA[384 + tid];
        if (row0 + tid < B) out[(size_t)B * 64 + row0 + tid] = v;
    }

    // ---- masked-column copy ----
    for (int i = tid; i < 1024; i += THREADS) {
        int row = i >> 3, j = i & 7;
        if (row0 + row < B)
            *(float4*)(out + (row0 + row) * 64 + j * 4) =
                *(const float4*)(x + (row0 + row) * 64 + j * 4);
    }
}

// ---------------------------------------------------------------------------
extern "C" void kernel_launch(void* const* d_in, const int* in_sizes, int n_in,
                              void* d_out, int out_size)
{
    const float* x  = (const float*)d_in[0];
    const float* W1 = (const float*)d_in[1];
    const float* b1 = (const float*)d_in[2];
    const float* W2 = (const float*)d_in[3];
    const float* b2 = (const float*)d_in[4];
    const float* W3 = (const float*)d_in[5];
    const float* b3 = (const float*)d_in[6];
    const float* W4 = (const float*)d_in[7];
    const float* b4 = (const float*)d_in[8];
    float* out = (float*)d_out;

    const int B = in_sizes[0] / 64;

    prep_weights<<<(WPK_TOT + 255) / 256, 256>>>(W1, W2, W3, W4);

    cudaFuncSetAttribute(rqs_mma_kernel,
                         cudaFuncAttributeMaxDynamicSharedMemorySize, SMEM_BYTES);
    const int grid = (B + 127) / 128;
    rqs_mma_kernel<<<grid, THREADS, SMEM_BYTES>>>(x, b1, b2, b3, b4, out, B);
}

// round 15
// speedup vs baseline: 1.2830x; 1.0473x over previous
#include <cuda_runtime.h>
#include <cuda_fp16.h>
#include <cstdint>

// ===========================================================================
// MaskedCouplingRQS — Round 15: R14 + smem-staged x_trans/y (XTR, stride 33,
// conflict-free) and a single coalesced 64-col output flush. Deletes all
// scattered epilogue LDG/STG. Numerics identical to R14.
// ===========================================================================

#define THREADS 512
#define SA_H 160
#define SRP  132
#define SXT  33                       // XTR stride (floats): 33 % 32 == 1

// ---- smem byte offsets ----
#define A_B    0                      // 128*160*2 = 40960
#define P_B    40960                  // 104*132*4 = 54912
#define XT_B   95872                  // 128*33*4  = 16896
#define B1_B   112768
#define B2_B   113280
#define B3_B   113792
#define B4_B   114304                 // 800*4
#define LD_B   117504                 // 512*4
#define SMEM_BYTES 119552

// ---- packed fp16 weights: contiguous 256-half fragments (R14 layout) ----
#define WPK_W1 0
#define WPK_W2 4096
#define WPK_W3 20480
#define WPK_W4 36864
#define W4_CH  13312
#define WPK_TOT 143360
__device__ __half g_wpk[WPK_TOT];

// --------------------------- helpers ---------------------------------------
__device__ __forceinline__ void mma16(float* c, uint32_t a0, uint32_t a1,
                                      uint32_t a2, uint32_t a3,
                                      uint32_t b0, uint32_t b1) {
    asm volatile(
        "mma.sync.aligned.m16n8k16.row.col.f32.f16.f16.f32 "
        "{%0,%1,%2,%3}, {%4,%5,%6,%7}, {%8,%9}, {%0,%1,%2,%3};"
        : "+f"(c[0]), "+f"(c[1]), "+f"(c[2]), "+f"(c[3])
        : "r"(a0), "r"(a1), "r"(a2), "r"(a3), "r"(b0), "r"(b1));
}
__device__ __forceinline__ float softplus_f(float v) {
    return fmaxf(v, 0.f) + __logf(1.f + __expf(-fabsf(v)));
}
__device__ __forceinline__ int hpos(int k) {
    int rel = k & 31;
    return ((k >> 5) << 5) + (((rel >> 1) & 3) << 3) + ((rel >> 3) << 1) + (rel & 1);
}

// ---------------------------------------------------------------------------
// prep: pack weights to fp16 in contiguous-fragment order (R14-verified).
// ---------------------------------------------------------------------------
__global__ void prep_weights(const float* __restrict__ W1, const float* __restrict__ W2,
                             const float* __restrict__ W3, const float* __restrict__ W4)
{
    int idx = blockIdx.x * blockDim.x + threadIdx.x;
    if (idx >= WPK_TOT) return;
    float v;
    if (idx < WPK_W2) {                               // W1: 16 frags, NKG=1
        int f = idx >> 8, e = idx & 255;
        int lane = e >> 3, h8 = e & 7;
        int n = f * 8 + (lane >> 2);
        int mm = lane & 3;
        int k = 2 * mm + (h8 & 1) + 8 * (h8 >> 1);
        v = W1[n * 32 + k];
    } else if (idx < WPK_W4) {                        // W2/W3: k0,k1; NKG=2
        int t = idx - WPK_W2;
        const float* W = (t < 16384) ? W2 : W3;
        int r = t & 16383;
        int kh = r >> 13, rr = r & 8191;
        int f = rr >> 8, e = rr & 255;
        int lane = e >> 3, h8 = e & 7;
        int ntl = f >> 1, kg = f & 1;
        int n = ntl * 8 + (lane >> 2);
        int mm = lane & 3;
        int kl = kg * 32 + 2 * mm + (h8 & 1) + 8 * (h8 >> 1);
        v = W[n * 128 + kh * 64 + kl];
    } else {                                          // W4: 8 x (k0,k1); NKG=2
        int t = idx - WPK_W4;
        int c = t / W4_CH, r = t - c * W4_CH;
        int kh = (r >= 6656) ? 1 : 0;
        int rr = kh ? r - 6656 : r;
        int f = rr >> 8, e = rr & 255;
        int lane = e >> 3, h8 = e & 7;
        int ntl = f >> 1, kg = f & 1;
        int n = ntl * 8 + (lane >> 2);
        int mm = lane & 3;
        int kl = kg * 32 + 2 * mm + (h8 & 1) + 8 * (h8 >> 1);
        v = (n < 100) ? W4[(size_t)(c * 100 + n) * 128 + kh * 64 + kl] : 0.f;
    }
    g_wpk[idx] = __float2half_rn(v);
}

// ---------------------------------------------------------------------------
// MMA: A from smem, W from global contiguous fragments.
template<int NT, int KG>
__device__ __forceinline__ void mma_ldg(const __half* a0p, const __half* a1p,
                                        const __half* __restrict__ wg, float* C) {
    #pragma unroll
    for (int kg = 0; kg < KG; kg++) {
        uint4 X0 = *(const uint4*)(a0p + kg * 32);
        uint4 Y0 = *(const uint4*)(a0p + 8 * SA_H + kg * 32);
        uint4 X1 = *(const uint4*)(a1p + kg * 32);
        uint4 Y1 = *(const uint4*)(a1p + 8 * SA_H + kg * 32);
        #pragma unroll
        for (int nt = 0; nt < NT; nt++) {
            uint4 Wv = __ldg((const uint4*)(wg + (nt * KG + kg) * 256));
            mma16(C + nt * 8,     X0.x, Y0.x, X0.y, Y0.y, Wv.x, Wv.y);
            mma16(C + nt * 8,     X0.z, Y0.z, X0.w, Y0.w, Wv.z, Wv.w);
            mma16(C + nt * 8 + 4, X1.x, Y1.x, X1.y, Y1.y, Wv.x, Wv.y);
            mma16(C + nt * 8 + 4, X1.z, Y1.z, X1.w, Y1.w, Wv.z, Wv.w);
        }
    }
}

// relu(C + bias) -> packed fp16 A (own 32 rows x own 32-col group)
__device__ __forceinline__ void relu_store2(const float* C, const float* bs,
                                            __half* Ah, int R0, int ng) {
    const int lane = threadIdx.x & 31;
    const int g = lane >> 2, m = lane & 3;
    #pragma unroll
    for (int mt = 0; mt < 2; mt++) {
        const int rb = R0 + mt * 16;
        #pragma unroll
        for (int nt = 0; nt < 4; nt++) {
            const int ntg = nt + ng * 4;
            const int c0 = ntg * 8 + 2 * m;
            const float b0 = bs[c0], b1 = bs[c0 + 1];
            const int off = ((ntg >> 2) << 5) + (m << 3) + ((ntg & 3) << 1);
            const float* Cc = C + nt * 8 + mt * 4;
            *(__half2*)(Ah + (rb + g) * SA_H + off) =
                __floats2half2_rn(fmaxf(Cc[0] + b0, 0.f), fmaxf(Cc[1] + b1, 0.f));
            *(__half2*)(Ah + (rb + g + 8) * SA_H + off) =
                __floats2half2_rn(fmaxf(Cc[2] + b0, 0.f), fmaxf(Cc[3] + b1, 0.f));
        }
    }
}

// column-major P store: P[col*SRP + row]
template<int NT>
__device__ __forceinline__ void p_store2(const float* C, float* P, int R0, int colbase) {
    const int lane = threadIdx.x & 31;
    const int g = lane >> 2, m = lane & 3;
    #pragma unroll
    for (int mt = 0; mt < 2; mt++) {
        const int rb = R0 + mt * 16;
        #pragma unroll
        for (int nt = 0; nt < NT; nt++) {
            const int c0 = colbase + nt * 8 + 2 * m;
            const float* Cc = C + nt * 8 + mt * 4;
            P[c0 * SRP + rb + g]           = Cc[0];
            P[(c0 + 1) * SRP + rb + g]     = Cc[1];
            P[c0 * SRP + rb + g + 8]       = Cc[2];
            P[(c0 + 1) * SRP + rb + g + 8] = Cc[3];
        }
    }
}

// ---------------------------------------------------------------------------
__global__ __launch_bounds__(THREADS, 1)
void rqs_mma_kernel(const float* __restrict__ x,
                    const float* __restrict__ b1, const float* __restrict__ b2,
                    const float* __restrict__ b3, const float* __restrict__ b4,
                    float* __restrict__ out, int B)
{
    extern __shared__ char smem[];
    __half* Ah  = (__half*)(smem + A_B);
    float*  Psm = (float*)(smem + P_B);
    float*  XTR = (float*)(smem + XT_B);
    float*  B1S = (float*)(smem + B1_B);
    float*  B2S = (float*)(smem + B2_B);
    float*  B3S = (float*)(smem + B3_B);
    float*  B4S = (float*)(smem + B4_B);
    float*  LDA = (float*)(smem + LD_B);

    const int tid  = threadIdx.x;
    const int lane = tid & 31;
    const int g    = lane >> 2, m = lane & 3;
    const int warp = tid >> 5;
    const int rg   = warp & 3;            // rowgroup (32 rows)
    const int ng   = warp >> 2;           // n-group (0..3)
    const int R0   = rg * 32;
    const long row0 = (long)blockIdx.x * 128;

    // layer4 tile split {4,3,3,3}
    const int tb4 = (ng == 0) ? 0 : (3 * ng + 1);
    const int cb4 = tb4 * 8;

    const __half* aw0 = Ah + (R0 + g) * SA_H + m * 8;
    const __half* aw1 = aw0 + 16 * SA_H;
    const __half* gw  = g_wpk;

    // per-warp global W fragment bases (contiguous-fragment layout)
    const __half* w1g  = gw + WPK_W1        + ng * 4 * 256 + lane * 8;
    const __half* w2g0 = gw + WPK_W2        + ng * 4 * 512 + lane * 8;
    const __half* w2g1 = gw + WPK_W2 + 8192 + ng * 4 * 512 + lane * 8;
    const __half* w3g0 = gw + WPK_W3        + ng * 4 * 512 + lane * 8;
    const __half* w3g1 = gw + WPK_W3 + 8192 + ng * 4 * 512 + lane * 8;
    const __half* w4gb = gw + WPK_W4        + tb4 * 512    + lane * 8;

    // ---- prologue: x_masked -> packed fp16 A ; x_trans -> XTR ; biases ----
    for (int i = tid; i < 1024; i += THREADS) {
        int row = i >> 3, j = i & 7;
        float4 v = make_float4(0.f, 0.f, 0.f, 0.f);
        if (row0 + row < B) v = *(const float4*)(x + (row0 + row) * 64 + j * 4);
        __half* Ar = Ah + row * SA_H;
        Ar[hpos(j * 4 + 0)] = __float2half_rn(v.x);
        Ar[hpos(j * 4 + 1)] = __float2half_rn(v.y);
        Ar[hpos(j * 4 + 2)] = __float2half_rn(v.z);
        Ar[hpos(j * 4 + 3)] = __float2half_rn(v.w);
    }
    for (int i = tid; i < 1024; i += THREADS) {        // x_trans (cols 32..63)
        int row = i >> 3, j = i & 7;
        float4 v = make_float4(0.f, 0.f, 0.f, 0.f);
        if (row0 + row < B) v = *(const float4*)(x + (row0 + row) * 64 + 32 + j * 4);
        float* Xr = XTR + row * SXT + j * 4;
        Xr[0] = v.x; Xr[1] = v.y; Xr[2] = v.z; Xr[3] = v.w;
    }
    if (tid < 128) {
        B1S[tid] = b1[tid];
        B2S[tid] = b2[tid];
        B3S[tid] = b3[tid];
    }
    for (int i = tid; i < 800; i += THREADS) B4S[i] = b4[i];
    __syncthreads();

    float C[32];

    // ================= Layer 1 (K=32) =================
    #pragma unroll
    for (int i = 0; i < 32; i++) C[i] = 0.f;
    mma_ldg<4, 1>(aw0, aw1, w1g, C);
    __syncthreads();
    relu_store2(C, B1S, Ah, R0, ng);                   // h1
    __syncthreads();

    // ================= Layer 2 =================
    #pragma unroll
    for (int i = 0; i < 32; i++) C[i] = 0.f;
    mma_ldg<4, 2>(aw0,      aw1,      w2g0, C);
    mma_ldg<4, 2>(aw0 + 64, aw1 + 64, w2g1, C);
    __syncthreads();
    relu_store2(C, B2S, Ah, R0, ng);                   // h2
    __syncthreads();

    // ================= Layer 3 =================
    #pragma unroll
    for (int i = 0; i < 32; i++) C[i] = 0.f;
    mma_ldg<4, 2>(aw0,      aw1,      w3g0, C);
    mma_ldg<4, 2>(aw0 + 64, aw1 + 64, w3g1, C);
    __syncthreads();
    relu_store2(C, B3S, Ah, R0, ng);                   // h3
    __syncthreads();

    // ================= Layer 4 + spline, 8 chunks =================
    const float MINB = 1e-4f;
    const float FREE = 10.f - 8.f * 1e-4f;
    const int q    = warp & 3;                         // epilogue dim
    const int erow = (warp >> 2) * 32 + lane;          // epilogue row
    float ldsum = 0.f;

    #pragma unroll 1
    for (int c = 0; c < 8; c++) {
        const __half* wk0 = w4gb + c * W4_CH;
        const __half* wk1 = wk0 + 6656;

        #pragma unroll
        for (int i = 0; i < 32; i++) C[i] = 0.f;

        if (ng == 0) {
            mma_ldg<4, 2>(aw0,      aw1,      wk0, C);
            mma_ldg<4, 2>(aw0 + 64, aw1 + 64, wk1, C);
        } else {
            mma_ldg<3, 2>(aw0,      aw1,      wk0, C);
            mma_ldg<3, 2>(aw0 + 64, aw1 + 64, wk1, C);
        }
        __syncthreads();                               // prior epilogue P reads done
        if (ng == 0) p_store2<4>(C, Psm, R0, cb4);
        else         p_store2<3>(C, Psm, R0, cb4);
        __syncthreads();

        // -------- spline epilogue: 1 task/thread, all smem --------
        {
            const int t = c * 4 + q;

            float acc[25];
            #pragma unroll
            for (int p = 0; p < 25; p++)
                acc[p] = Psm[(q * 25 + p) * SRP + erow] + B4S[c * 100 + q * 25 + p];

            float mx = acc[0];
            #pragma unroll
            for (int i = 1; i < 8; i++) mx = fmaxf(mx, acc[i]);
            float wdt[8]; float Sw = 0.f;
            #pragma unroll
            for (int i = 0; i < 8; i++) { wdt[i] = __expf(acc[i] - mx); Sw += wdt[i]; }
            float mh = acc[8];
            #pragma unroll
            for (int i = 9; i < 16; i++) mh = fmaxf(mh, acc[i]);
            float hgt[8]; float Sh = 0.f;
            #pragma unroll
            for (int i = 0; i < 8; i++) { hgt[i] = __expf(acc[8 + i] - mh); Sh += hgt[i]; }
            const float fw = FREE / Sw, fh = FREE / Sh;
            #pragma unroll
            for (int i = 0; i < 8; i++) {
                wdt[i] = MINB + wdt[i] * fw;
                hgt[i] = MINB + hgt[i] * fh;
            }

            const float xt = XTR[erow * SXT + t];
            const float xc = fminf(fmaxf(xt, -5.f), 5.f);
            const bool inside = (xt >= -5.f) && (xt <= 5.f);

            int idx = 0; float cum = -5.f, xk = -5.f, wk = wdt[0];
            #pragma unroll
            for (int i = 0; i < 7; i++) {
                cum += wdt[i];
                if (xc >= cum) { idx = i + 1; xk = cum; wk = wdt[i + 1]; }
            }
            float cumh = -5.f, yk = -5.f, hk = hgt[0];
            #pragma unroll
            for (int i = 0; i < 7; i++) {
                cumh += hgt[i];
                if (idx > i) { yk = cumh; hk = hgt[i + 1]; }
            }
            float sA = acc[16], sB = acc[17];
            #pragma unroll
            for (int i = 1; i < 8; i++)
                if (idx >= i) { sA = acc[16 + i]; sB = acc[17 + i]; }
            const float dk  = 1e-4f + softplus_f(sA);
            const float dk1 = 1e-4f + softplus_f(sB);

            const float rwk  = 1.f / wk;
            const float xi   = (xc - xk) * rwk;
            const float om   = 1.f - xi;
            const float sk   = hk * rwk;
            const float xiom = xi * om;
            const float den  = sk + (dk1 + dk - 2.f * sk) * xiom;
            const float rden = 1.f / den;
            const float num  = sk * xi * xi + dk * xiom;
            const float y_in = yk + hk * num * rden;
            const float num2 = dk1 * xi * xi + 2.f * sk * xiom + dk * om * om;
            const float ld_in = __logf(sk * sk * num2 * rden * rden);

            XTR[erow * SXT + t] = inside ? y_in : xt;  // y in place (own slot)
            ldsum += inside ? ld_in : 0.f;
        }
    }

    // ---- logdet: 4 dim-partials per row via smem ----
    LDA[q * 128 + erow] = ldsum;
    __syncthreads();                                   // also orders XTR y-writes
    if (tid < 128) {
        float v = LDA[tid] + LDA[128 + tid] + LDA[256 + tid] + LDA[384 + tid];
        if (row0 + tid < B) out[(size_t)B * 64 + row0 + tid] = v;
    }

    // ---- single coalesced flush: [x_masked | y_trans] ----
    for (int i = tid; i < 2048; i += THREADS) {
        int row = i >> 4, c4 = i & 15;
        if (row0 + row >= B) continue;
        float4 v;
        if (c4 < 8) {
            v = *(const float4*)(x + (row0 + row) * 64 + c4 * 4);
        } else {
            const float* Xr = XTR + row * SXT + (c4 - 8) * 4;
            v = make_float4(Xr[0], Xr[1], Xr[2], Xr[3]);
        }
        *(float4*)(out + (row0 + row) * 64 + c4 * 4) = v;
    }
}

// ---------------------------------------------------------------------------
extern "C" void kernel_launch(void* const* d_in, const int* in_sizes, int n_in,
                              void* d_out, int out_size)
{
    const float* x  = (const float*)d_in[0];
    const float* W1 = (const float*)d_in[1];
    const float* b1 = (const float*)d_in[2];
    const float* W2 = (const float*)d_in[3];
    const float* b2 = (const float*)d_in[4];
    const float* W3 = (const float*)d_in[5];
    const float* b3 = (const float*)d_in[6];
    const float* W4 = (const float*)d_in[7];
    const float* b4 = (const float*)d_in[8];
    float* out = (float*)d_out;

    const int B = in_sizes[0] / 64;

    prep_weights<<<(WPK_TOT + 255) / 256, 256>>>(W1, W2, W3, W4);

    cudaFuncSetAttribute(rqs_mma_kernel,
                         cudaFuncAttributeMaxDynamicSharedMemorySize, SMEM_BYTES);
    const int grid = (B + 127) / 128;
    rqs_mma_kernel<<<grid, THREADS, SMEM_BYTES>>>(x, b1, b2, b3, b4, out, B);
}

// round 16
// speedup vs baseline: 1.3197x; 1.0286x over previous
#include <cuda_runtime.h>
#include <cuda_fp16.h>
#include <cstdint>

// ===========================================================================
// MaskedCouplingRQS — Round 16: R15 + scoped barriers.
//  * layers 1-3: A handoff is private to the 4 warps sharing rg ->
//    bar.sync(rg+1, 128) instead of full __syncthreads (6 syncs rescoped)
//  * layer 4: double-buffered P -> one full sync per chunk (8 syncs deleted)
// Numerics bit-identical to R15 (canary rel_err 0.00045069).
// ===========================================================================

#define THREADS 512
#define SA_H 160
#define SRP  132
#define SXT  33

// ---- smem byte offsets ----
#define A_B    0                      // 128*160*2 = 40960
#define P0_B   40960                  // 104*132*4 = 54912
#define P1_B   95872                  // 54912
#define XT_B   150784                 // 128*33*4  = 16896
#define B1_B   167680
#define B2_B   168192
#define B3_B   168704
#define B4_B   169216                 // 800*4
#define LD_B   172416                 // 512*4
#define SMEM_BYTES 174464

// ---- packed fp16 weights: contiguous 256-half fragments (R14 layout) ----
#define WPK_W1 0
#define WPK_W2 4096
#define WPK_W3 20480
#define WPK_W4 36864
#define W4_CH  13312
#define WPK_TOT 143360
__device__ __half g_wpk[WPK_TOT];

// --------------------------- helpers ---------------------------------------
__device__ __forceinline__ void mma16(float* c, uint32_t a0, uint32_t a1,
                                      uint32_t a2, uint32_t a3,
                                      uint32_t b0, uint32_t b1) {
    asm volatile(
        "mma.sync.aligned.m16n8k16.row.col.f32.f16.f16.f32 "
        "{%0,%1,%2,%3}, {%4,%5,%6,%7}, {%8,%9}, {%0,%1,%2,%3};"
        : "+f"(c[0]), "+f"(c[1]), "+f"(c[2]), "+f"(c[3])
        : "r"(a0), "r"(a1), "r"(a2), "r"(a3), "r"(b0), "r"(b1));
}
__device__ __forceinline__ void bar_group(int id) {   // 128-thread scoped barrier
    asm volatile("bar.sync %0, 128;" :: "r"(id) : "memory");
}
__device__ __forceinline__ float softplus_f(float v) {
    return fmaxf(v, 0.f) + __logf(1.f + __expf(-fabsf(v)));
}
__device__ __forceinline__ int hpos(int k) {
    int rel = k & 31;
    return ((k >> 5) << 5) + (((rel >> 1) & 3) << 3) + ((rel >> 3) << 1) + (rel & 1);
}

// ---------------------------------------------------------------------------
// prep: pack weights to fp16 in contiguous-fragment order (R14-verified).
// ---------------------------------------------------------------------------
__global__ void prep_weights(const float* __restrict__ W1, const float* __restrict__ W2,
                             const float* __restrict__ W3, const float* __restrict__ W4)
{
    int idx = blockIdx.x * blockDim.x + threadIdx.x;
    if (idx >= WPK_TOT) return;
    float v;
    if (idx < WPK_W2) {                               // W1: 16 frags, NKG=1
        int f = idx >> 8, e = idx & 255;
        int lane = e >> 3, h8 = e & 7;
        int n = f * 8 + (lane >> 2);
        int mm = lane & 3;
        int k = 2 * mm + (h8 & 1) + 8 * (h8 >> 1);
        v = W1[n * 32 + k];
    } else if (idx < WPK_W4) {                        // W2/W3: k0,k1; NKG=2
        int t = idx - WPK_W2;
        const float* W = (t < 16384) ? W2 : W3;
        int r = t & 16383;
        int kh = r >> 13, rr = r & 8191;
        int f = rr >> 8, e = rr & 255;
        int lane = e >> 3, h8 = e & 7;
        int ntl = f >> 1, kg = f & 1;
        int n = ntl * 8 + (lane >> 2);
        int mm = lane & 3;
        int kl = kg * 32 + 2 * mm + (h8 & 1) + 8 * (h8 >> 1);
        v = W[n * 128 + kh * 64 + kl];
    } else {                                          // W4: 8 x (k0,k1); NKG=2
        int t = idx - WPK_W4;
        int c = t / W4_CH, r = t - c * W4_CH;
        int kh = (r >= 6656) ? 1 : 0;
        int rr = kh ? r - 6656 : r;
        int f = rr >> 8, e = rr & 255;
        int lane = e >> 3, h8 = e & 7;
        int ntl = f >> 1, kg = f & 1;
        int n = ntl * 8 + (lane >> 2);
        int mm = lane & 3;
        int kl = kg * 32 + 2 * mm + (h8 & 1) + 8 * (h8 >> 1);
        v = (n < 100) ? W4[(size_t)(c * 100 + n) * 128 + kh * 64 + kl] : 0.f;
    }
    g_wpk[idx] = __float2half_rn(v);
}

// ---------------------------------------------------------------------------
// MMA: A from smem, W from global contiguous fragments.
template<int NT, int KG>
__device__ __forceinline__ void mma_ldg(const __half* a0p, const __half* a1p,
                                        const __half* __restrict__ wg, float* C) {
    #pragma unroll
    for (int kg = 0; kg < KG; kg++) {
        uint4 X0 = *(const uint4*)(a0p + kg * 32);
        uint4 Y0 = *(const uint4*)(a0p + 8 * SA_H + kg * 32);
        uint4 X1 = *(const uint4*)(a1p + kg * 32);
        uint4 Y1 = *(const uint4*)(a1p + 8 * SA_H + kg * 32);
        #pragma unroll
        for (int nt = 0; nt < NT; nt++) {
            uint4 Wv = __ldg((const uint4*)(wg + (nt * KG + kg) * 256));
            mma16(C + nt * 8,     X0.x, Y0.x, X0.y, Y0.y, Wv.x, Wv.y);
            mma16(C + nt * 8,     X0.z, Y0.z, X0.w, Y0.w, Wv.z, Wv.w);
            mma16(C + nt * 8 + 4, X1.x, Y1.x, X1.y, Y1.y, Wv.x, Wv.y);
            mma16(C + nt * 8 + 4, X1.z, Y1.z, X1.w, Y1.w, Wv.z, Wv.w);
        }
    }
}

// relu(C + bias) -> packed fp16 A (own 32 rows x own 32-col group)
__device__ __forceinline__ void relu_store2(const float* C, const float* bs,
                                            __half* Ah, int R0, int ng) {
    const int lane = threadIdx.x & 31;
    const int g = lane >> 2, m = lane & 3;
    #pragma unroll
    for (int mt = 0; mt < 2; mt++) {
        const int rb = R0 + mt * 16;
        #pragma unroll
        for (int nt = 0; nt < 4; nt++) {
            const int ntg = nt + ng * 4;
            const int c0 = ntg * 8 + 2 * m;
            const float b0 = bs[c0], b1 = bs[c0 + 1];
            const int off = ((ntg >> 2) << 5) + (m << 3) + ((ntg & 3) << 1);
            const float* Cc = C + nt * 8 + mt * 4;
            *(__half2*)(Ah + (rb + g) * SA_H + off) =
                __floats2half2_rn(fmaxf(Cc[0] + b0, 0.f), fmaxf(Cc[1] + b1, 0.f));
            *(__half2*)(Ah + (rb + g + 8) * SA_H + off) =
                __floats2half2_rn(fmaxf(Cc[2] + b0, 0.f), fmaxf(Cc[3] + b1, 0.f));
        }
    }
}

// column-major P store: P[col*SRP + row]
template<int NT>
__device__ __forceinline__ void p_store2(const float* C, float* P, int R0, int colbase) {
    const int lane = threadIdx.x & 31;
    const int g = lane >> 2, m = lane & 3;
    #pragma unroll
    for (int mt = 0; mt < 2; mt++) {
        const int rb = R0 + mt * 16;
        #pragma unroll
        for (int nt = 0; nt < NT; nt++) {
            const int c0 = colbase + nt * 8 + 2 * m;
            const float* Cc = C + nt * 8 + mt * 4;
            P[c0 * SRP + rb + g]           = Cc[0];
            P[(c0 + 1) * SRP + rb + g]     = Cc[1];
            P[c0 * SRP + rb + g + 8]       = Cc[2];
            P[(c0 + 1) * SRP + rb + g + 8] = Cc[3];
        }
    }
}

// ---------------------------------------------------------------------------
__global__ __launch_bounds__(THREADS, 1)
void rqs_mma_kernel(const float* __restrict__ x,
                    const float* __restrict__ b1, const float* __restrict__ b2,
                    const float* __restrict__ b3, const float* __restrict__ b4,
                    float* __restrict__ out, int B)
{
    extern __shared__ char smem[];
    __half* Ah  = (__half*)(smem + A_B);
    float*  Ps0 = (float*)(smem + P0_B);
    float*  Ps1 = (float*)(smem + P1_B);
    float*  XTR = (float*)(smem + XT_B);
    float*  B1S = (float*)(smem + B1_B);
    float*  B2S = (float*)(smem + B2_B);
    float*  B3S = (float*)(smem + B3_B);
    float*  B4S = (float*)(smem + B4_B);
    float*  LDA = (float*)(smem + LD_B);

    const int tid  = threadIdx.x;
    const int lane = tid & 31;
    const int g    = lane >> 2, m = lane & 3;
    const int warp = tid >> 5;
    const int rg   = warp & 3;            // rowgroup (32 rows)
    const int ng   = warp >> 2;           // n-group (0..3)
    const int R0   = rg * 32;
    const int bid  = rg + 1;              // named barrier id (0 reserved)
    const long row0 = (long)blockIdx.x * 128;

    // layer4 tile split {4,3,3,3}
    const int tb4 = (ng == 0) ? 0 : (3 * ng + 1);
    const int cb4 = tb4 * 8;

    const __half* aw0 = Ah + (R0 + g) * SA_H + m * 8;
    const __half* aw1 = aw0 + 16 * SA_H;
    const __half* gw  = g_wpk;

    // per-warp global W fragment bases (contiguous-fragment layout)
    const __half* w1g  = gw + WPK_W1        + ng * 4 * 256 + lane * 8;
    const __half* w2g0 = gw + WPK_W2        + ng * 4 * 512 + lane * 8;
    const __half* w2g1 = gw + WPK_W2 + 8192 + ng * 4 * 512 + lane * 8;
    const __half* w3g0 = gw + WPK_W3        + ng * 4 * 512 + lane * 8;
    const __half* w3g1 = gw + WPK_W3 + 8192 + ng * 4 * 512 + lane * 8;
    const __half* w4gb = gw + WPK_W4        + tb4 * 512    + lane * 8;

    // ---- prologue: x_masked -> packed fp16 A ; x_trans -> XTR ; biases ----
    for (int i = tid; i < 1024; i += THREADS) {
        int row = i >> 3, j = i & 7;
        float4 v = make_float4(0.f, 0.f, 0.f, 0.f);
        if (row0 + row < B) v = *(const float4*)(x + (row0 + row) * 64 + j * 4);
        __half* Ar = Ah + row * SA_H;
        Ar[hpos(j * 4 + 0)] = __float2half_rn(v.x);
        Ar[hpos(j * 4 + 1)] = __float2half_rn(v.y);
        Ar[hpos(j * 4 + 2)] = __float2half_rn(v.z);
        Ar[hpos(j * 4 + 3)] = __float2half_rn(v.w);
    }
    for (int i = tid; i < 1024; i += THREADS) {        // x_trans (cols 32..63)
        int row = i >> 3, j = i & 7;
        float4 v = make_float4(0.f, 0.f, 0.f, 0.f);
        if (row0 + row < B) v = *(const float4*)(x + (row0 + row) * 64 + 32 + j * 4);
        float* Xr = XTR + row * SXT + j * 4;
        Xr[0] = v.x; Xr[1] = v.y; Xr[2] = v.z; Xr[3] = v.w;
    }
    if (tid < 128) {
        B1S[tid] = b1[tid];
        B2S[tid] = b2[tid];
        B3S[tid] = b3[tid];
    }
    for (int i = tid; i < 800; i += THREADS) B4S[i] = b4[i];
    __syncthreads();

    float C[32];

    // ================= Layer 1 (K=32) =================
    #pragma unroll
    for (int i = 0; i < 32; i++) C[i] = 0.f;
    mma_ldg<4, 1>(aw0, aw1, w1g, C);
    bar_group(bid);                       // rg-group: A rows R0 reads done
    relu_store2(C, B1S, Ah, R0, ng);      // h1
    bar_group(bid);                       // rg-group: h1 rows R0 visible

    // ================= Layer 2 =================
    #pragma unroll
    for (int i = 0; i < 32; i++) C[i] = 0.f;
    mma_ldg<4, 2>(aw0,      aw1,      w2g0, C);
    mma_ldg<4, 2>(aw0 + 64, aw1 + 64, w2g1, C);
    bar_group(bid);
    relu_store2(C, B2S, Ah, R0, ng);      // h2
    bar_group(bid);

    // ================= Layer 3 =================
    #pragma unroll
    for (int i = 0; i < 32; i++) C[i] = 0.f;
    mma_ldg<4, 2>(aw0,      aw1,      w3g0, C);
    mma_ldg<4, 2>(aw0 + 64, aw1 + 64, w3g1, C);
    bar_group(bid);
    relu_store2(C, B3S, Ah, R0, ng);      // h3
    bar_group(bid);

    // ================= Layer 4 + spline, 8 chunks (double-buffered P) ======
    const float MINB = 1e-4f;
    const float FREE = 10.f - 8.f * 1e-4f;
    const int q    = warp & 3;                         // epilogue dim
    const int erow = (warp >> 2) * 32 + lane;          // epilogue row
    float ldsum = 0.f;

    #pragma unroll 1
    for (int c = 0; c < 8; c++) {
        float* Pc = (c & 1) ? Ps1 : Ps0;
        const __half* wk0 = w4gb + c * W4_CH;
        const __half* wk1 = wk0 + 6656;

        #pragma unroll
        for (int i = 0; i < 32; i++) C[i] = 0.f;

        if (ng == 0) {
            mma_ldg<4, 2>(aw0,      aw1,      wk0, C);
            mma_ldg<4, 2>(aw0 + 64, aw1 + 64, wk1, C);
        } else {
            mma_ldg<3, 2>(aw0,      aw1,      wk0, C);
            mma_ldg<3, 2>(aw0 + 64, aw1 + 64, wk1, C);
        }
        if (ng == 0) p_store2<4>(C, Pc, R0, cb4);
        else         p_store2<3>(C, Pc, R0, cb4);
        __syncthreads();                               // the ONE sync per chunk

        // -------- spline epilogue: 1 task/thread, all smem --------
        {
            const int t = c * 4 + q;

            float acc[25];
            #pragma unroll
            for (int p = 0; p < 25; p++)
                acc[p] = Pc[(q * 25 + p) * SRP + erow] + B4S[c * 100 + q * 25 + p];

            float mx = acc[0];
            #pragma unroll
            for (int i = 1; i < 8; i++) mx = fmaxf(mx, acc[i]);
            float wdt[8]; float Sw = 0.f;
            #pragma unroll
            for (int i = 0; i < 8; i++) { wdt[i] = __expf(acc[i] - mx); Sw += wdt[i]; }
            float mh = acc[8];
            #pragma unroll
            for (int i = 9; i < 16; i++) mh = fmaxf(mh, acc[i]);
            float hgt[8]; float Sh = 0.f;
            #pragma unroll
            for (int i = 0; i < 8; i++) { hgt[i] = __expf(acc[8 + i] - mh); Sh += hgt[i]; }
            const float fw = FREE / Sw, fh = FREE / Sh;
            #pragma unroll
            for (int i = 0; i < 8; i++) {
                wdt[i] = MINB + wdt[i] * fw;
                hgt[i] = MINB + hgt[i] * fh;
            }

            const float xt = XTR[erow * SXT + t];
            const float xc = fminf(fmaxf(xt, -5.f), 5.f);
            const bool inside = (xt >= -5.f) && (xt <= 5.f);

            int idx = 0; float cum = -5.f, xk = -5.f, wk = wdt[0];
            #pragma unroll
            for (int i = 0; i < 7; i++) {
                cum += wdt[i];
                if (xc >= cum) { idx = i + 1; xk = cum; wk = wdt[i + 1]; }
            }
            float cumh = -5.f, yk = -5.f, hk = hgt[0];
            #pragma unroll
            for (int i = 0; i < 7; i++) {
                cumh += hgt[i];
                if (idx > i) { yk = cumh; hk = hgt[i + 1]; }
            }
            float sA = acc[16], sB = acc[17];
            #pragma unroll
            for (int i = 1; i < 8; i++)
                if (idx >= i) { sA = acc[16 + i]; sB = acc[17 + i]; }
            const float dk  = 1e-4f + softplus_f(sA);
            const float dk1 = 1e-4f + softplus_f(sB);

            const float rwk  = 1.f / wk;
            const float xi   = (xc - xk) * rwk;
            const float om   = 1.f - xi;
            const float sk   = hk * rwk;
            const float xiom = xi * om;
            const float den  = sk + (dk1 + dk - 2.f * sk) * xiom;
            const float rden = 1.f / den;
            const float num  = sk * xi * xi + dk * xiom;
            const float y_in = yk + hk * num * rden;
            const float num2 = dk1 * xi * xi + 2.f * sk * xiom + dk * om * om;
            const float ld_in = __logf(sk * sk * num2 * rden * rden);

            XTR[erow * SXT + t] = inside ? y_in : xt;  // y in place (own slot)
            ldsum += inside ? ld_in : 0.f;
        }
    }

    // ---- logdet: 4 dim-partials per row via smem ----
    LDA[q * 128 + erow] = ldsum;
    __syncthreads();                                   // also orders XTR y-writes
    if (tid < 128) {
        float v = LDA[tid] + LDA[128 + tid] + LDA[256 + tid] + LDA[384 + tid];
        if (row0 + tid < B) out[(size_t)B * 64 + row0 + tid] = v;
    }

    // ---- single coalesced flush: [x_masked | y_trans] ----
    for (int i = tid; i < 2048; i += THREADS) {
        int row = i >> 4, c4 = i & 15;
        if (row0 + row >= B) continue;
        float4 v;
        if (c4 < 8) {
            v = *(const float4*)(x + (row0 + row) * 64 + c4 * 4);
        } else {
            const float* Xr = XTR + row * SXT + (c4 - 8) * 4;
            v = make_float4(Xr[0], Xr[1], Xr[2], Xr[3]);
        }
        *(float4*)(out + (row0 + row) * 64 + c4 * 4) = v;
    }
}

// ---------------------------------------------------------------------------
extern "C" void kernel_launch(void* const* d_in, const int* in_sizes, int n_in,
                              void* d_out, int out_size)
{
    const float* x  = (const float*)d_in[0];
    const float* W1 = (const float*)d_in[1];
    const float* b1 = (const float*)d_in[2];
    const float* W2 = (const float*)d_in[3];
    const float* b2 = (const float*)d_in[4];
    const float* W3 = (const float*)d_in[5];
    const float* b3 = (const float*)d_in[6];
    const float* W4 = (const float*)d_in[7];
    const float* b4 = (const float*)d_in[8];
    float* out = (float*)d_out;

    const int B = in_sizes[0] / 64;

    prep_weights<<<(WPK_TOT + 255) / 256, 256>>>(W1, W2, W3, W4);

    cudaFuncSetAttribute(rqs_mma_kernel,
                         cudaFuncAttributeMaxDynamicSharedMemorySize, SMEM_BYTES);
    const int grid = (B + 127) / 128;
    rqs_mma_kernel<<<grid, THREADS, SMEM_BYTES>>>(x, b1, b2, b3, b4, out, B);
}

// round 17
// speedup vs baseline: 1.3731x; 1.0404x over previous
#include <cuda_runtime.h>
#include <cuda_fp16.h>
#include <cstdint>

// ===========================================================================
// MaskedCouplingRQS — Round 17: R16 + epilogue instruction diet.
//  * one merged select chain (single FSETP/bin drives xk,yk,wk,hk,sA,sB)
//  * layer-4 bias pre-loaded into MMA accumulators (epilogue drops 25 LDS
//    + 25 FADD per task)
// ===========================================================================

#define THREADS 512
#define SA_H 160
#define SRP  132
#define SXT  33

// ---- smem byte offsets ----
#define A_B    0                      // 128*160*2 = 40960
#define P0_B   40960                  // 104*132*4 = 54912
#define P1_B   95872                  // 54912
#define XT_B   150784                 // 128*33*4  = 16896
#define B1_B   167680
#define B2_B   168192
#define B3_B   168704
#define B4_B   169216                 // 800*4
#define LD_B   172416                 // 512*4
#define SMEM_BYTES 174464

// ---- packed fp16 weights: contiguous 256-half fragments (R14 layout) ----
#define WPK_W1 0
#define WPK_W2 4096
#define WPK_W3 20480
#define WPK_W4 36864
#define W4_CH  13312
#define WPK_TOT 143360
__device__ __half g_wpk[WPK_TOT];

// --------------------------- helpers ---------------------------------------
__device__ __forceinline__ void mma16(float* c, uint32_t a0, uint32_t a1,
                                      uint32_t a2, uint32_t a3,
                                      uint32_t b0, uint32_t b1) {
    asm volatile(
        "mma.sync.aligned.m16n8k16.row.col.f32.f16.f16.f32 "
        "{%0,%1,%2,%3}, {%4,%5,%6,%7}, {%8,%9}, {%0,%1,%2,%3};"
        : "+f"(c[0]), "+f"(c[1]), "+f"(c[2]), "+f"(c[3])
        : "r"(a0), "r"(a1), "r"(a2), "r"(a3), "r"(b0), "r"(b1));
}
__device__ __forceinline__ void bar_group(int id) {
    asm volatile("bar.sync %0, 128;" :: "r"(id) : "memory");
}
__device__ __forceinline__ float softplus_f(float v) {
    return fmaxf(v, 0.f) + __logf(1.f + __expf(-fabsf(v)));
}
__device__ __forceinline__ int hpos(int k) {
    int rel = k & 31;
    return ((k >> 5) << 5) + (((rel >> 1) & 3) << 3) + ((rel >> 3) << 1) + (rel & 1);
}

// ---------------------------------------------------------------------------
// prep: pack weights to fp16 in contiguous-fragment order (R14-verified).
// ---------------------------------------------------------------------------
__global__ void prep_weights(const float* __restrict__ W1, const float* __restrict__ W2,
                             const float* __restrict__ W3, const float* __restrict__ W4)
{
    int idx = blockIdx.x * blockDim.x + threadIdx.x;
    if (idx >= WPK_TOT) return;
    float v;
    if (idx < WPK_W2) {                               // W1: 16 frags, NKG=1
        int f = idx >> 8, e = idx & 255;
        int lane = e >> 3, h8 = e & 7;
        int n = f * 8 + (lane >> 2);
        int mm = lane & 3;
        int k = 2 * mm + (h8 & 1) + 8 * (h8 >> 1);
        v = W1[n * 32 + k];
    } else if (idx < WPK_W4) {                        // W2/W3: k0,k1; NKG=2
        int t = idx - WPK_W2;
        const float* W = (t < 16384) ? W2 : W3;
        int r = t & 16383;
        int kh = r >> 13, rr = r & 8191;
        int f = rr >> 8, e = rr & 255;
        int lane = e >> 3, h8 = e & 7;
        int ntl = f >> 1, kg = f & 1;
        int n = ntl * 8 + (lane >> 2);
        int mm = lane & 3;
        int kl = kg * 32 + 2 * mm + (h8 & 1) + 8 * (h8 >> 1);
        v = W[n * 128 + kh * 64 + kl];
    } else {                                          // W4: 8 x (k0,k1); NKG=2
        int t = idx - WPK_W4;
        int c = t / W4_CH, r = t - c * W4_CH;
        int kh = (r >= 6656) ? 1 : 0;
        int rr = kh ? r - 6656 : r;
        int f = rr >> 8, e = rr & 255;
        int lane = e >> 3, h8 = e & 7;
        int ntl = f >> 1, kg = f & 1;
        int n = ntl * 8 + (lane >> 2);
        int mm = lane & 3;
        int kl = kg * 32 + 2 * mm + (h8 & 1) + 8 * (h8 >> 1);
        v = (n < 100) ? W4[(size_t)(c * 100 + n) * 128 + kh * 64 + kl] : 0.f;
    }
    g_wpk[idx] = __float2half_rn(v);
}

// ---------------------------------------------------------------------------
// MMA: A from smem, W from global contiguous fragments.
template<int NT, int KG>
__device__ __forceinline__ void mma_ldg(const __half* a0p, const __half* a1p,
                                        const __half* __restrict__ wg, float* C) {
    #pragma unroll
    for (int kg = 0; kg < KG; kg++) {
        uint4 X0 = *(const uint4*)(a0p + kg * 32);
        uint4 Y0 = *(const uint4*)(a0p + 8 * SA_H + kg * 32);
        uint4 X1 = *(const uint4*)(a1p + kg * 32);
        uint4 Y1 = *(const uint4*)(a1p + 8 * SA_H + kg * 32);
        #pragma unroll
        for (int nt = 0; nt < NT; nt++) {
            uint4 Wv = __ldg((const uint4*)(wg + (nt * KG + kg) * 256));
            mma16(C + nt * 8,     X0.x, Y0.x, X0.y, Y0.y, Wv.x, Wv.y);
            mma16(C + nt * 8,     X0.z, Y0.z, X0.w, Y0.w, Wv.z, Wv.w);
            mma16(C + nt * 8 + 4, X1.x, Y1.x, X1.y, Y1.y, Wv.x, Wv.y);
            mma16(C + nt * 8 + 4, X1.z, Y1.z, X1.w, Y1.w, Wv.z, Wv.w);
        }
    }
}

// relu(C + bias) -> packed fp16 A (own 32 rows x own 32-col group)
__device__ __forceinline__ void relu_store2(const float* C, const float* bs,
                                            __half* Ah, int R0, int ng) {
    const int lane = threadIdx.x & 31;
    const int g = lane >> 2, m = lane & 3;
    #pragma unroll
    for (int mt = 0; mt < 2; mt++) {
        const int rb = R0 + mt * 16;
        #pragma unroll
        for (int nt = 0; nt < 4; nt++) {
            const int ntg = nt + ng * 4;
            const int c0 = ntg * 8 + 2 * m;
            const float b0 = bs[c0], b1 = bs[c0 + 1];
            const int off = ((ntg >> 2) << 5) + (m << 3) + ((ntg & 3) << 1);
            const float* Cc = C + nt * 8 + mt * 4;
            *(__half2*)(Ah + (rb + g) * SA_H + off) =
                __floats2half2_rn(fmaxf(Cc[0] + b0, 0.f), fmaxf(Cc[1] + b1, 0.f));
            *(__half2*)(Ah + (rb + g + 8) * SA_H + off) =
                __floats2half2_rn(fmaxf(Cc[2] + b0, 0.f), fmaxf(Cc[3] + b1, 0.f));
        }
    }
}

// column-major P store: P[col*SRP + row]
template<int NT>
__device__ __forceinline__ void p_store2(const float* C, float* P, int R0, int colbase) {
    const int lane = threadIdx.x & 31;
    const int g = lane >> 2, m = lane & 3;
    #pragma unroll
    for (int mt = 0; mt < 2; mt++) {
        const int rb = R0 + mt * 16;
        #pragma unroll
        for (int nt = 0; nt < NT; nt++) {
            const int c0 = colbase + nt * 8 + 2 * m;
            const float* Cc = C + nt * 8 + mt * 4;
            P[c0 * SRP + rb + g]           = Cc[0];
            P[(c0 + 1) * SRP + rb + g]     = Cc[1];
            P[c0 * SRP + rb + g + 8]       = Cc[2];
            P[(c0 + 1) * SRP + rb + g + 8] = Cc[3];
        }
    }
}

// init C with layer-4 bias (column-dependent; padded cols -> 0)
template<int NT>
__device__ __forceinline__ void c_init_bias(float* C, const float* B4S,
                                            int c, int cb4, int m) {
    #pragma unroll
    for (int nt = 0; nt < NT; nt++) {
        const int c0 = cb4 + nt * 8 + 2 * m;
        const float b0 = (c0     < 100) ? B4S[c * 100 + c0]     : 0.f;
        const float b1 = (c0 + 1 < 100) ? B4S[c * 100 + c0 + 1] : 0.f;
        C[nt*8+0] = b0; C[nt*8+1] = b1; C[nt*8+2] = b0; C[nt*8+3] = b1;
        C[nt*8+4] = b0; C[nt*8+5] = b1; C[nt*8+6] = b0; C[nt*8+7] = b1;
    }
}

// ---------------------------------------------------------------------------
__global__ __launch_bounds__(THREADS, 1)
void rqs_mma_kernel(const float* __restrict__ x,
                    const float* __restrict__ b1, const float* __restrict__ b2,
                    const float* __restrict__ b3, const float* __restrict__ b4,
                    float* __restrict__ out, int B)
{
    extern __shared__ char smem[];
    __half* Ah  = (__half*)(smem + A_B);
    float*  Ps0 = (float*)(smem + P0_B);
    float*  Ps1 = (float*)(smem + P1_B);
    float*  XTR = (float*)(smem + XT_B);
    float*  B1S = (float*)(smem + B1_B);
    float*  B2S = (float*)(smem + B2_B);
    float*  B3S = (float*)(smem + B3_B);
    float*  B4S = (float*)(smem + B4_B);
    float*  LDA = (float*)(smem + LD_B);

    const int tid  = threadIdx.x;
    const int lane = tid & 31;
    const int g    = lane >> 2, m = lane & 3;
    const int warp = tid >> 5;
    const int rg   = warp & 3;            // rowgroup (32 rows)
    const int ng   = warp >> 2;           // n-group (0..3)
    const int R0   = rg * 32;
    const int bid  = rg + 1;              // named barrier id
    const long row0 = (long)blockIdx.x * 128;

    // layer4 tile split {4,3,3,3}
    const int tb4 = (ng == 0) ? 0 : (3 * ng + 1);
    const int cb4 = tb4 * 8;

    const __half* aw0 = Ah + (R0 + g) * SA_H + m * 8;
    const __half* aw1 = aw0 + 16 * SA_H;
    const __half* gw  = g_wpk;

    // per-warp global W fragment bases (contiguous-fragment layout)
    const __half* w1g  = gw + WPK_W1        + ng * 4 * 256 + lane * 8;
    const __half* w2g0 = gw + WPK_W2        + ng * 4 * 512 + lane * 8;
    const __half* w2g1 = gw + WPK_W2 + 8192 + ng * 4 * 512 + lane * 8;
    const __half* w3g0 = gw + WPK_W3        + ng * 4 * 512 + lane * 8;
    const __half* w3g1 = gw + WPK_W3 + 8192 + ng * 4 * 512 + lane * 8;
    const __half* w4gb = gw + WPK_W4        + tb4 * 512    + lane * 8;

    // ---- prologue: x_masked -> packed fp16 A ; x_trans -> XTR ; biases ----
    for (int i = tid; i < 1024; i += THREADS) {
        int row = i >> 3, j = i & 7;
        float4 v = make_float4(0.f, 0.f, 0.f, 0.f);
        if (row0 + row < B) v = *(const float4*)(x + (row0 + row) * 64 + j * 4);
        __half* Ar = Ah + row * SA_H;
        Ar[hpos(j * 4 + 0)] = __float2half_rn(v.x);
        Ar[hpos(j * 4 + 1)] = __float2half_rn(v.y);
        Ar[hpos(j * 4 + 2)] = __float2half_rn(v.z);
        Ar[hpos(j * 4 + 3)] = __float2half_rn(v.w);
    }
    for (int i = tid; i < 1024; i += THREADS) {        // x_trans (cols 32..63)
        int row = i >> 3, j = i & 7;
        float4 v = make_float4(0.f, 0.f, 0.f, 0.f);
        if (row0 + row < B) v = *(const float4*)(x + (row0 + row) * 64 + 32 + j * 4);
        float* Xr = XTR + row * SXT + j * 4;
        Xr[0] = v.x; Xr[1] = v.y; Xr[2] = v.z; Xr[3] = v.w;
    }
    if (tid < 128) {
        B1S[tid] = b1[tid];
        B2S[tid] = b2[tid];
        B3S[tid] = b3[tid];
    }
    for (int i = tid; i < 800; i += THREADS) B4S[i] = b4[i];
    __syncthreads();

    float C[32];

    // ================= Layer 1 (K=32) =================
    #pragma unroll
    for (int i = 0; i < 32; i++) C[i] = 0.f;
    mma_ldg<4, 1>(aw0, aw1, w1g, C);
    bar_group(bid);
    relu_store2(C, B1S, Ah, R0, ng);      // h1
    bar_group(bid);

    // ================= Layer 2 =================
    #pragma unroll
    for (int i = 0; i < 32; i++) C[i] = 0.f;
    mma_ldg<4, 2>(aw0,      aw1,      w2g0, C);
    mma_ldg<4, 2>(aw0 + 64, aw1 + 64, w2g1, C);
    bar_group(bid);
    relu_store2(C, B2S, Ah, R0, ng);      // h2
    bar_group(bid);

    // ================= Layer 3 =================
    #pragma unroll
    for (int i = 0; i < 32; i++) C[i] = 0.f;
    mma_ldg<4, 2>(aw0,      aw1,      w3g0, C);
    mma_ldg<4, 2>(aw0 + 64, aw1 + 64, w3g1, C);
    bar_group(bid);
    relu_store2(C, B3S, Ah, R0, ng);      // h3
    bar_group(bid);

    // ================= Layer 4 + spline, 8 chunks (double-buffered P) ======
    const float MINB = 1e-4f;
    const float FREE = 10.f - 8.f * 1e-4f;
    const int q    = warp & 3;                         // epilogue dim
    const int erow = (warp >> 2) * 32 + lane;          // epilogue row
    float ldsum = 0.f;

    #pragma unroll 1
    for (int c = 0; c < 8; c++) {
        float* Pc = (c & 1) ? Ps1 : Ps0;
        const __half* wk0 = w4gb + c * W4_CH;
        const __half* wk1 = wk0 + 6656;

        if (ng == 0) {
            c_init_bias<4>(C, B4S, c, cb4, m);
            mma_ldg<4, 2>(aw0,      aw1,      wk0, C);
            mma_ldg<4, 2>(aw0 + 64, aw1 + 64, wk1, C);
            p_store2<4>(C, Pc, R0, cb4);
        } else {
            c_init_bias<3>(C, B4S, c, cb4, m);
            mma_ldg<3, 2>(aw0,      aw1,      wk0, C);
            mma_ldg<3, 2>(aw0 + 64, aw1 + 64, wk1, C);
            p_store2<3>(C, Pc, R0, cb4);
        }
        __syncthreads();                               // the ONE sync per chunk

        // -------- spline epilogue: 1 task/thread, all smem --------
        {
            const int t = c * 4 + q;

            float acc[25];
            #pragma unroll
            for (int p = 0; p < 25; p++)
                acc[p] = Pc[(q * 25 + p) * SRP + erow];   // bias already in P

            float mx = acc[0];
            #pragma unroll
            for (int i = 1; i < 8; i++) mx = fmaxf(mx, acc[i]);
            float wdt[8]; float Sw = 0.f;
            #pragma unroll
            for (int i = 0; i < 8; i++) { wdt[i] = __expf(acc[i] - mx); Sw += wdt[i]; }
            float mh = acc[8];
            #pragma unroll
            for (int i = 9; i < 16; i++) mh = fmaxf(mh, acc[i]);
            float hgt[8]; float Sh = 0.f;
            #pragma unroll
            for (int i = 0; i < 8; i++) { hgt[i] = __expf(acc[8 + i] - mh); Sh += hgt[i]; }
            const float fw = FREE / Sw, fh = FREE / Sh;
            #pragma unroll
            for (int i = 0; i < 8; i++) {
                wdt[i] = MINB + wdt[i] * fw;
                hgt[i] = MINB + hgt[i] * fh;
            }

            const float xt = XTR[erow * SXT + t];
            const float xc = fminf(fmaxf(xt, -5.f), 5.f);
            const bool inside = (xt >= -5.f) && (xt <= 5.f);

            // ---- merged select chain: one predicate drives all six ----
            float cum  = -5.f + wdt[0];
            float cumh = -5.f + hgt[0];
            float xk = -5.f, yk = -5.f, wk = wdt[0], hk = hgt[0];
            float sA = acc[16], sB = acc[17];
            #pragma unroll
            for (int i = 0; i < 7; i++) {
                if (xc >= cum) {
                    xk = cum;  yk = cumh;
                    wk = wdt[i + 1]; hk = hgt[i + 1];
                    sA = acc[17 + i]; sB = acc[18 + i];
                }
                cum  += wdt[i + 1];
                cumh += hgt[i + 1];
            }

            const float dk  = 1e-4f + softplus_f(sA);
            const float dk1 = 1e-4f + softplus_f(sB);

            const float rwk  = 1.f / wk;
            const float xi   = (xc - xk) * rwk;
            const float om   = 1.f - xi;
            const float sk   = hk * rwk;
            const float xiom = xi * om;
            const float den  = sk + (dk1 + dk - 2.f * sk) * xiom;
            const float rden = 1.f / den;
            const float num  = sk * xi * xi + dk * xiom;
            const float y_in = yk + hk * num * rden;
            const float num2 = dk1 * xi * xi + 2.f * sk * xiom + dk * om * om;
            const float ld_in = __logf(sk * sk * num2 * rden * rden);

            XTR[erow * SXT + t] = inside ? y_in : xt;  // y in place (own slot)
            ldsum += inside ? ld_in : 0.f;
        }
    }

    // ---- logdet: 4 dim-partials per row via smem ----
    LDA[q * 128 + erow] = ldsum;
    __syncthreads();                                   // also orders XTR y-writes
    if (tid < 128) {
        float v = LDA[tid] + LDA[128 + tid] + LDA[256 + tid] + LDA[384 + tid];
        if (row0 + tid < B) out[(size_t)B * 64 + row0 + tid] = v;
    }

    // ---- single coalesced flush: [x_masked | y_trans] ----
    for (int i = tid; i < 2048; i += THREADS) {
        int row = i >> 4, c4 = i & 15;
        if (row0 + row >= B) continue;
        float4 v;
        if (c4 < 8) {
            v = *(const float4*)(x + (row0 + row) * 64 + c4 * 4);
        } else {
            const float* Xr = XTR + row * SXT + (c4 - 8) * 4;
            v = make_float4(Xr[0], Xr[1], Xr[2], Xr[3]);
        }
        *(float4*)(out + (row0 + row) * 64 + c4 * 4) = v;
    }
}

// ---------------------------------------------------------------------------
extern "C" void kernel_launch(void* const* d_in, const int* in_sizes, int n_in,
                              void* d_out, int out_size)
{
    const float* x  = (const float*)d_in[0];
    const float* W1 = (const float*)d_in[1];
    const float* b1 = (const float*)d_in[2];
    const float* W2 = (const float*)d_in[3];
    const float* b2 = (const float*)d_in[4];
    const float* W3 = (const float*)d_in[5];
    const float* b3 = (const float*)d_in[6];
    const float* W4 = (const float*)d_in[7];
    const float* b4 = (const float*)d_in[8];
    float* out = (float*)d_out;

    const int B = in_sizes[0] / 64;

    prep_weights<<<(WPK_TOT + 255) / 256, 256>>>(W1, W2, W3, W4);

    cudaFuncSetAttribute(rqs_mma_kernel,
                         cudaFuncAttributeMaxDynamicSharedMemorySize, SMEM_BYTES);
    const int grid = (B + 127) / 128;
    rqs_mma_kernel<<<grid, THREADS, SMEM_BYTES>>>(x, b1, b2, b3, b4, out, B);
}